// round 1
// baseline (speedup 1.0000x reference)
#include <cuda_runtime.h>
#include <math.h>
#include <stdint.h>

#define N_NODES 4096
#define N_HID   512
#define N_INF   512
#define N_S     10

// ---------------- scratch (static device globals; no allocation) ----------------
__device__ float g_fts[4][N_NODES * N_HID];          // seq@W^T results
__device__ float g_h[4][N_NODES * N_HID];            // h1..h4
__device__ float g_Z[N_NODES * N_HID];               // h1+h2
__device__ float g_G[N_HID * N_HID];                 // Z^T Z (split-K atomic)
__device__ float g_node_sq[(size_t)N_NODES * N_NODES]; // (Zn Zn^T)^2 entries
__device__ float g_csum[2][N_HID];                   // column sums of h1,h2
__device__ float g_u[2][N_HID];                      // Wd @ c1, Wd @ c2
__device__ float g_rninv[N_NODES];                   // 1/max(rownorm(Z),1e-12)
__device__ float g_cninv[N_HID];                     // 1/max(colnorm(Z),1e-12)
__device__ float g_feat_loss;
__device__ float g_node_loss;

// ---------------- init: zero atomically-accumulated buffers ----------------
__global__ void k_init() {
    int i = blockIdx.x * blockDim.x + threadIdx.x;
    if (i < N_HID * N_HID) g_G[i] = 0.0f;
    if (i == 0) { g_feat_loss = 0.0f; g_node_loss = 0.0f; }
}

// ---------------- GEMM 1: fts = seq @ W^T  (NT, M=4096,N=512,K=512) ----------------
__global__ __launch_bounds__(256) void k_gemm_fts(
    const float* __restrict__ seq1, const float* __restrict__ seq2,
    const float* __restrict__ W1,   const float* __restrict__ W2)
{
    const int z = blockIdx.z;
    const float* __restrict__ A = (z & 2) ? seq2 : seq1;  // [M,K] row-major
    const float* __restrict__ B = (z & 1) ? W2 : W1;      // [N,K] row-major
    float* __restrict__ C = g_fts[z];

    __shared__ float As[8][128];
    __shared__ float Bs[8][128];

    const int t = threadIdx.x;
    const int ldrow = t >> 1;
    const int ldseg = (t & 1) * 4;
    const int tn = (t & 15) * 8;
    const int tm = (t >> 4) * 8;
    const int gmB = blockIdx.y * 128;
    const int gnB = blockIdx.x * 128;

    float acc[8][8];
#pragma unroll
    for (int i = 0; i < 8; i++)
#pragma unroll
        for (int j = 0; j < 8; j++) acc[i][j] = 0.0f;

    for (int k0 = 0; k0 < N_INF; k0 += 8) {
        float4 av = *reinterpret_cast<const float4*>(A + (size_t)(gmB + ldrow) * N_INF + k0 + ldseg);
        float4 bv = *reinterpret_cast<const float4*>(B + (size_t)(gnB + ldrow) * N_INF + k0 + ldseg);
        As[ldseg + 0][ldrow] = av.x; As[ldseg + 1][ldrow] = av.y;
        As[ldseg + 2][ldrow] = av.z; As[ldseg + 3][ldrow] = av.w;
        Bs[ldseg + 0][ldrow] = bv.x; Bs[ldseg + 1][ldrow] = bv.y;
        Bs[ldseg + 2][ldrow] = bv.z; Bs[ldseg + 3][ldrow] = bv.w;
        __syncthreads();
#pragma unroll
        for (int kk = 0; kk < 8; kk++) {
            float a[8], b[8];
#pragma unroll
            for (int i = 0; i < 8; i++) a[i] = As[kk][tm + i];
#pragma unroll
            for (int j = 0; j < 8; j++) b[j] = Bs[kk][tn + j];
#pragma unroll
            for (int i = 0; i < 8; i++)
#pragma unroll
                for (int j = 0; j < 8; j++) acc[i][j] += a[i] * b[j];
        }
        __syncthreads();
    }
#pragma unroll
    for (int i = 0; i < 8; i++) {
#pragma unroll
        for (int j4 = 0; j4 < 8; j4 += 4) {
            float4 v = make_float4(acc[i][j4], acc[i][j4 + 1], acc[i][j4 + 2], acc[i][j4 + 3]);
            *reinterpret_cast<float4*>(C + (size_t)(gmB + tm + i) * N_HID + gnB + tn + j4) = v;
        }
    }
}

// ---------------- GEMM 2: h = prelu(A @ fts + b)  (NN, M=4096,N=512,K=4096) -------
__global__ __launch_bounds__(256) void k_gemm_prop(
    const float* __restrict__ adj, const float* __restrict__ diff,
    const float* __restrict__ b1,  const float* __restrict__ b2,
    const float* __restrict__ a1,  const float* __restrict__ a2)
{
    const int z = blockIdx.z;
    const float* __restrict__ A = (z & 1) ? diff : adj;   // [M,K] row-major, ld=4096
    const float* __restrict__ B = g_fts[z];               // [K,N] row-major, ld=512
    const float* __restrict__ bias = (z & 1) ? b2 : b1;
    const float slope = (z & 1) ? a2[0] : a1[0];
    float* __restrict__ C = g_h[z];

    __shared__ float As[8][128];
    __shared__ float Bs[8][128];

    const int t = threadIdx.x;
    const int ldrow = t >> 1;
    const int ldseg = (t & 1) * 4;
    const int bkr = t >> 5;
    const int bcc = (t & 31) * 4;
    const int tn = (t & 15) * 8;
    const int tm = (t >> 4) * 8;
    const int gmB = blockIdx.y * 128;
    const int gnB = blockIdx.x * 128;

    float acc[8][8];
#pragma unroll
    for (int i = 0; i < 8; i++)
#pragma unroll
        for (int j = 0; j < 8; j++) acc[i][j] = 0.0f;

    for (int k0 = 0; k0 < N_NODES; k0 += 8) {
        float4 av = *reinterpret_cast<const float4*>(A + (size_t)(gmB + ldrow) * N_NODES + k0 + ldseg);
        As[ldseg + 0][ldrow] = av.x; As[ldseg + 1][ldrow] = av.y;
        As[ldseg + 2][ldrow] = av.z; As[ldseg + 3][ldrow] = av.w;
        float4 bv = *reinterpret_cast<const float4*>(B + (size_t)(k0 + bkr) * N_HID + gnB + bcc);
        *reinterpret_cast<float4*>(&Bs[bkr][bcc]) = bv;
        __syncthreads();
#pragma unroll
        for (int kk = 0; kk < 8; kk++) {
            float a[8], b[8];
#pragma unroll
            for (int i = 0; i < 8; i++) a[i] = As[kk][tm + i];
#pragma unroll
            for (int j = 0; j < 8; j++) b[j] = Bs[kk][tn + j];
#pragma unroll
            for (int i = 0; i < 8; i++)
#pragma unroll
                for (int j = 0; j < 8; j++) acc[i][j] += a[i] * b[j];
        }
        __syncthreads();
    }
#pragma unroll
    for (int i = 0; i < 8; i++) {
#pragma unroll
        for (int j = 0; j < 8; j++) {
            float v = acc[i][j] + bias[gnB + tn + j];
            v = (v >= 0.0f) ? v : slope * v;
            C[(size_t)(gmB + tm + i) * N_HID + gnB + tn + j] = v;
        }
    }
}

// ---------------- Z = h1 + h2, row inv-norms ----------------
__global__ void k_compute_Z() {
    const int r = blockIdx.x;
    const int c = threadIdx.x;
    float z = g_h[0][(size_t)r * N_HID + c] + g_h[1][(size_t)r * N_HID + c];
    g_Z[(size_t)r * N_HID + c] = z;
    __shared__ float red[512];
    red[c] = z * z;
    __syncthreads();
    for (int s = 256; s > 0; s >>= 1) {
        if (c < s) red[c] += red[c + s];
        __syncthreads();
    }
    if (c == 0) g_rninv[r] = 1.0f / fmaxf(sqrtf(red[0]), 1e-12f);
}

// ---------------- column reductions: colsum(h1), colsum(h2), colsumsq(Z) ----------
__global__ void k_col_reduce() {
    const int mode = blockIdx.y;           // 0: h1 sum, 1: h2 sum, 2: Z sumsq
    const int tx = threadIdx.x & 31;
    const int ty = threadIdx.x >> 5;       // 0..7
    const int col = blockIdx.x * 32 + tx;
    const float* __restrict__ src = (mode == 0) ? g_h[0] : (mode == 1) ? g_h[1] : g_Z;
    float s = 0.0f;
    for (int r = ty; r < N_NODES; r += 8) {
        float v = src[(size_t)r * N_HID + col];
        s += (mode == 2) ? v * v : v;
    }
    __shared__ float sm[8][32];
    sm[ty][tx] = s;
    __syncthreads();
    if (ty == 0) {
        float tot = 0.0f;
#pragma unroll
        for (int k = 0; k < 8; k++) tot += sm[k][tx];
        if (mode == 2) g_cninv[col] = 1.0f / fmaxf(sqrtf(tot), 1e-12f);
        else g_csum[mode][col] = tot;
    }
}

// ---------------- u = Wd @ sigmoid(colmean) ----------------
__global__ void k_compute_u(const float* __restrict__ Wd) {
    __shared__ float c1s[512], c2s[512];
    const int h = threadIdx.x;
    c1s[h] = 1.0f / (1.0f + expf(-g_csum[0][h] * (1.0f / 4096.0f)));
    c2s[h] = 1.0f / (1.0f + expf(-g_csum[1][h] * (1.0f / 4096.0f)));
    __syncthreads();
    float u1 = 0.0f, u2 = 0.0f;
    const float4* Wrow = reinterpret_cast<const float4*>(Wd + (size_t)h * N_HID);
#pragma unroll 4
    for (int k4 = 0; k4 < 128; k4++) {
        float4 w = Wrow[k4];
        int k = k4 * 4;
        u1 += w.x * c1s[k] + w.y * c1s[k + 1] + w.z * c1s[k + 2] + w.w * c1s[k + 3];
        u2 += w.x * c2s[k] + w.y * c2s[k + 1] + w.z * c2s[k + 2] + w.w * c2s[k + 3];
    }
    g_u[0][h] = u1;
    g_u[1][h] = u2;
}

// ---------------- ret[q*N + n] = h_x[n,:] . u_y + bd ----------------
__global__ void k_ret(const float* __restrict__ bd, float* __restrict__ out) {
    const int q = blockIdx.y;                                 // 0..3
    const int n = blockIdx.x * 8 + (threadIdx.x >> 5);
    const int lane = threadIdx.x & 31;
    const float* __restrict__ h = (q == 0) ? g_h[1] : (q == 1) ? g_h[0]
                                : (q == 2) ? g_h[3] : g_h[2];
    const float* __restrict__ u = (q == 0 || q == 2) ? g_u[0] : g_u[1];
    float s = 0.0f;
    for (int k = lane; k < N_HID; k += 32)
        s += h[(size_t)n * N_HID + k] * u[k];
#pragma unroll
    for (int o = 16; o > 0; o >>= 1) s += __shfl_down_sync(0xFFFFFFFFu, s, o);
    if (lane == 0) out[q * N_NODES + n] = s + bd[0];
}

// ---------------- GEMM 3: G = Z^T Z  (TN, 512x512xK=4096, split-K=32) ----------------
__global__ __launch_bounds__(256) void k_gemm_G() {
    __shared__ float As[8][128];
    __shared__ float Bs[8][128];
    const int t = threadIdx.x;
    const int kr = t >> 5;
    const int cc = (t & 31) * 4;
    const int tn = (t & 15) * 8;
    const int tm = (t >> 4) * 8;
    const int gmB = blockIdx.y * 128;
    const int gnB = blockIdx.x * 128;
    const int kBase = blockIdx.z * 128;

    float acc[8][8];
#pragma unroll
    for (int i = 0; i < 8; i++)
#pragma unroll
        for (int j = 0; j < 8; j++) acc[i][j] = 0.0f;

    for (int kt = 0; kt < 128; kt += 8) {
        const int k0 = kBase + kt;
        float4 av = *reinterpret_cast<const float4*>(g_Z + (size_t)(k0 + kr) * N_HID + gmB + cc);
        *reinterpret_cast<float4*>(&As[kr][cc]) = av;
        float4 bv = *reinterpret_cast<const float4*>(g_Z + (size_t)(k0 + kr) * N_HID + gnB + cc);
        *reinterpret_cast<float4*>(&Bs[kr][cc]) = bv;
        __syncthreads();
#pragma unroll
        for (int kk = 0; kk < 8; kk++) {
            float a[8], b[8];
#pragma unroll
            for (int i = 0; i < 8; i++) a[i] = As[kk][tm + i];
#pragma unroll
            for (int j = 0; j < 8; j++) b[j] = Bs[kk][tn + j];
#pragma unroll
            for (int i = 0; i < 8; i++)
#pragma unroll
                for (int j = 0; j < 8; j++) acc[i][j] += a[i] * b[j];
        }
        __syncthreads();
    }
#pragma unroll
    for (int i = 0; i < 8; i++)
#pragma unroll
        for (int j = 0; j < 8; j++)
            atomicAdd(&g_G[(size_t)(gmB + tm + i) * N_HID + gnB + tn + j], acc[i][j]);
}

// ---------------- feat loss: per feature row, sort 512 values ----------------
__global__ void k_feat_loss(const int* __restrict__ feat_index) {
    const int h = blockIdx.x;
    const int k = threadIdx.x;
    __shared__ float sv[512];
    float feat = g_G[(size_t)h * N_HID + k] * g_cninv[h] * g_cninv[k];
    sv[k] = feat * feat;
    __syncthreads();
    const float diag = sv[h];
    __syncthreads();
    // bitonic ascending, n = 512
    for (int kk = 2; kk <= 512; kk <<= 1) {
        for (int j = kk >> 1; j > 0; j >>= 1) {
            int i = k;
            int ixj = i ^ j;
            if (ixj > i) {
                float a = sv[i], b = sv[ixj];
                bool up = ((i & kk) == 0);
                if ((a > b) == up) { sv[i] = b; sv[ixj] = a; }
            }
            __syncthreads();
        }
    }
    if (k == 0) {
        float neg = 0.0f;
#pragma unroll
        for (int s = 0; s < N_S; s++) neg += expf(2.0f * sv[feat_index[s]]);
        float pos = expf(2.0f * diag);
        atomicAdd(&g_feat_loss, (logf(neg) - logf(pos)) * (1.0f / 512.0f));
    }
}

// ---------------- GEMM 4: node^2 = ((Zn Zn^T))^2  (NT, 4096x4096x512) --------------
__global__ __launch_bounds__(256) void k_gemm_node() {
    __shared__ float As[8][128];
    __shared__ float Bs[8][128];
    const int t = threadIdx.x;
    const int ldrow = t >> 1;
    const int ldseg = (t & 1) * 4;
    const int tn = (t & 15) * 8;
    const int tm = (t >> 4) * 8;
    const int gmB = blockIdx.y * 128;
    const int gnB = blockIdx.x * 128;

    float acc[8][8];
#pragma unroll
    for (int i = 0; i < 8; i++)
#pragma unroll
        for (int j = 0; j < 8; j++) acc[i][j] = 0.0f;

    for (int k0 = 0; k0 < N_HID; k0 += 8) {
        float4 av = *reinterpret_cast<const float4*>(g_Z + (size_t)(gmB + ldrow) * N_HID + k0 + ldseg);
        float4 bv = *reinterpret_cast<const float4*>(g_Z + (size_t)(gnB + ldrow) * N_HID + k0 + ldseg);
        As[ldseg + 0][ldrow] = av.x; As[ldseg + 1][ldrow] = av.y;
        As[ldseg + 2][ldrow] = av.z; As[ldseg + 3][ldrow] = av.w;
        Bs[ldseg + 0][ldrow] = bv.x; Bs[ldseg + 1][ldrow] = bv.y;
        Bs[ldseg + 2][ldrow] = bv.z; Bs[ldseg + 3][ldrow] = bv.w;
        __syncthreads();
#pragma unroll
        for (int kk = 0; kk < 8; kk++) {
            float a[8], b[8];
#pragma unroll
            for (int i = 0; i < 8; i++) a[i] = As[kk][tm + i];
#pragma unroll
            for (int j = 0; j < 8; j++) b[j] = Bs[kk][tn + j];
#pragma unroll
            for (int i = 0; i < 8; i++)
#pragma unroll
                for (int j = 0; j < 8; j++) acc[i][j] += a[i] * b[j];
        }
        __syncthreads();
    }
    float ri[8], rj[8];
#pragma unroll
    for (int i = 0; i < 8; i++) ri[i] = g_rninv[gmB + tm + i];
#pragma unroll
    for (int j = 0; j < 8; j++) rj[j] = g_rninv[gnB + tn + j];
#pragma unroll
    for (int i = 0; i < 8; i++) {
#pragma unroll
        for (int j4 = 0; j4 < 8; j4 += 4) {
            float4 v;
            float x0 = acc[i][j4 + 0] * ri[i] * rj[j4 + 0];
            float x1 = acc[i][j4 + 1] * ri[i] * rj[j4 + 1];
            float x2 = acc[i][j4 + 2] * ri[i] * rj[j4 + 2];
            float x3 = acc[i][j4 + 3] * ri[i] * rj[j4 + 3];
            v.x = x0 * x0; v.y = x1 * x1; v.z = x2 * x2; v.w = x3 * x3;
            *reinterpret_cast<float4*>(g_node_sq + (size_t)(gmB + tm + i) * N_NODES + gnB + tn + j4) = v;
        }
    }
}

// ---------------- node loss: per row, pos sum + bitonic sort 4096 ----------------
__global__ void k_node_row(const float* __restrict__ adj_label,
                           const int* __restrict__ node_index) {
    const int i = blockIdx.x;
    const int tid = threadIdx.x;
    __shared__ float sv[4096];
    __shared__ float red[512];
    const float* __restrict__ trow = g_node_sq + (size_t)i * N_NODES;
    const float* __restrict__ lrow = adj_label + (size_t)i * N_NODES;
    float pos = 0.0f;
    for (int j = tid; j < N_NODES; j += 512) {
        float t = trow[j];
        sv[j] = t;
        pos += expf(2.0f * t) * lrow[j];
    }
    red[tid] = pos;
    __syncthreads();
    for (int s = 256; s > 0; s >>= 1) {
        if (tid < s) red[tid] += red[tid + s];
        __syncthreads();
    }
    const float posSum = red[0];
    __syncthreads();
    // bitonic ascending, n = 4096, 512 threads (8 pairs each substage covers 2048 pairs)
    for (int kk = 2; kk <= 4096; kk <<= 1) {
        for (int j = kk >> 1; j > 0; j >>= 1) {
            for (int idx = tid; idx < 4096; idx += 512) {
                int ixj = idx ^ j;
                if (ixj > idx) {
                    float a = sv[idx], b = sv[ixj];
                    bool up = ((idx & kk) == 0);
                    if ((a > b) == up) { sv[idx] = b; sv[ixj] = a; }
                }
            }
            __syncthreads();
        }
    }
    if (tid == 0) {
        float neg = 0.0f;
#pragma unroll
        for (int s = 0; s < N_S; s++) neg += expf(2.0f * sv[node_index[s]]);
        atomicAdd(&g_node_loss, (logf(neg) - logf(posSum)) * (1.0f / 4096.0f));
    }
}

// ---------------- finalize ----------------
__global__ void k_finalize(float* __restrict__ out) {
    out[4 * N_NODES + 0] = g_feat_loss;
    out[4 * N_NODES + 1] = g_node_loss;
}

// ---------------- launch ----------------
extern "C" void kernel_launch(void* const* d_in, const int* in_sizes, int n_in,
                              void* d_out, int out_size) {
    const float* seq1      = (const float*)d_in[0];
    const float* seq2      = (const float*)d_in[1];
    const float* adj       = (const float*)d_in[2];
    const float* diff      = (const float*)d_in[3];
    const float* adj_label = (const float*)d_in[4];
    const int*   feat_idx  = (const int*)d_in[5];
    const int*   node_idx  = (const int*)d_in[6];
    const float* W1        = (const float*)d_in[7];
    const float* b1        = (const float*)d_in[8];
    const float* a1        = (const float*)d_in[9];
    const float* W2        = (const float*)d_in[10];
    const float* b2        = (const float*)d_in[11];
    const float* a2        = (const float*)d_in[12];
    const float* Wd        = (const float*)d_in[13];
    const float* bd        = (const float*)d_in[14];
    float* out = (float*)d_out;

    k_init<<<(N_HID * N_HID + 255) / 256, 256>>>();
    k_gemm_fts<<<dim3(4, 32, 4), 256>>>(seq1, seq2, W1, W2);
    k_gemm_prop<<<dim3(4, 32, 4), 256>>>(adj, diff, b1, b2, a1, a2);
    k_compute_Z<<<N_NODES, 512>>>();
    k_col_reduce<<<dim3(16, 3), 256>>>();
    k_compute_u<<<1, 512>>>(Wd);
    k_ret<<<dim3(512, 4), 256>>>(bd, out);
    k_gemm_G<<<dim3(4, 4, 32), 256>>>();
    k_feat_loss<<<512, 512>>>(feat_idx);
    k_gemm_node<<<dim3(32, 32), 256>>>();
    k_node_row<<<N_NODES, 512>>>(adj_label, node_idx);
    k_finalize<<<1, 1>>>(out);
}

// round 2
// speedup vs baseline: 2.0844x; 2.0844x over previous
#include <cuda_runtime.h>
#include <math.h>
#include <stdint.h>

#define N_NODES 4096
#define N_HID   512
#define N_INF   512
#define N_S     10

// ---------------- scratch (static device globals; no allocation) ----------------
__device__ float g_fts[4][N_NODES * N_HID];          // seq@W^T results
__device__ float g_h[4][N_NODES * N_HID];            // h1..h4
__device__ float g_Z[N_NODES * N_HID];               // h1+h2
__device__ float g_G[N_HID * N_HID];                 // Z^T Z (split-K atomic)
__device__ float g_node_sq[(size_t)N_NODES * N_NODES]; // (Zn Zn^T)^2 entries
__device__ float g_csum[2][N_HID];                   // column sums of h1,h2
__device__ float g_u[2][N_HID];                      // Wd @ c1, Wd @ c2
__device__ float g_rninv[N_NODES];                   // 1/max(rownorm(Z),1e-12)
__device__ float g_cninv[N_HID];                     // 1/max(colnorm(Z),1e-12)
__device__ float g_feat_loss;
__device__ float g_node_loss;

// ---------------- tf32 mma helpers ----------------
__device__ __forceinline__ unsigned f2tf32(float x) {
    unsigned r;
    asm("cvt.rna.tf32.f32 %0, %1;" : "=r"(r) : "f"(x));
    return r;
}

__device__ __forceinline__ void mma8(float (&c)[4], const unsigned (&a)[4],
                                     const unsigned (&b)[2]) {
    asm volatile(
        "mma.sync.aligned.m16n8k8.row.col.f32.tf32.tf32.f32 "
        "{%0,%1,%2,%3}, {%4,%5,%6,%7}, {%8,%9}, {%0,%1,%2,%3};\n"
        : "+f"(c[0]), "+f"(c[1]), "+f"(c[2]), "+f"(c[3])
        : "r"(a[0]), "r"(a[1]), "r"(a[2]), "r"(a[3]), "r"(b[0]), "r"(b[1]));
}

#define CVT_ST4(dst, row, seg, v)                        \
    dst[row][(seg) + 0] = f2tf32(v.x);                   \
    dst[row][(seg) + 1] = f2tf32(v.y);                   \
    dst[row][(seg) + 2] = f2tf32(v.z);                   \
    dst[row][(seg) + 3] = f2tf32(v.w);

// =========================================================================
// NT core: C[128,128] tile of A[M,K](row, K-contig) x B[N,K]^T(row, K-contig)
// =========================================================================
__device__ __forceinline__ void mma_nt_core(
    const float* __restrict__ A, int lda,
    const float* __restrict__ B, int ldb,
    int m0, int n0, int K, float (&acc)[4][4][4])
{
    __shared__ unsigned As[2][128][20];
    __shared__ unsigned Bs[2][128][20];
    const int t = threadIdx.x;
    const int lane = t & 31, warp = t >> 5;
    const int g = lane >> 2, t4 = lane & 3;
    const int wr = (warp & 1) * 64, wc = (warp >> 1) * 32;
    const int lrow = t >> 2, lseg = (t & 3) * 4;

    const float* Ab = A + (size_t)(m0 + lrow) * lda + lseg;
    const float* Bb = B + (size_t)(n0 + lrow) * ldb + lseg;

    {   // preload tile 0
        float4 a0 = *(const float4*)(Ab);
        float4 a1 = *(const float4*)(Ab + (size_t)64 * lda);
        float4 b0 = *(const float4*)(Bb);
        float4 b1 = *(const float4*)(Bb + (size_t)64 * ldb);
        CVT_ST4(As[0], lrow, lseg, a0); CVT_ST4(As[0], lrow + 64, lseg, a1);
        CVT_ST4(Bs[0], lrow, lseg, b0); CVT_ST4(Bs[0], lrow + 64, lseg, b1);
    }
    __syncthreads();
    const int KT = K >> 4;
    for (int kt = 0; kt < KT; kt++) {
        const int cur = kt & 1;
        float4 a0, a1, b0, b1;
        const bool pf = (kt + 1 < KT);
        if (pf) {
            const float* Ap = Ab + (kt + 1) * 16;
            const float* Bp = Bb + (kt + 1) * 16;
            a0 = *(const float4*)Ap; a1 = *(const float4*)(Ap + (size_t)64 * lda);
            b0 = *(const float4*)Bp; b1 = *(const float4*)(Bp + (size_t)64 * ldb);
        }
#pragma unroll
        for (int ks = 0; ks < 2; ks++) {
            const int k = ks * 8;
            unsigned af[4][4], bf[4][2];
#pragma unroll
            for (int mt = 0; mt < 4; mt++) {
                const int r = wr + mt * 16;
                af[mt][0] = As[cur][r + g][k + t4];
                af[mt][1] = As[cur][r + g + 8][k + t4];
                af[mt][2] = As[cur][r + g][k + t4 + 4];
                af[mt][3] = As[cur][r + g + 8][k + t4 + 4];
            }
#pragma unroll
            for (int nt = 0; nt < 4; nt++) {
                const int c = wc + nt * 8 + g;
                bf[nt][0] = Bs[cur][c][k + t4];
                bf[nt][1] = Bs[cur][c][k + t4 + 4];
            }
#pragma unroll
            for (int mt = 0; mt < 4; mt++)
#pragma unroll
                for (int nt = 0; nt < 4; nt++)
                    mma8(acc[mt][nt], af[mt], bf[nt]);
        }
        if (pf) {
            const int nxt = cur ^ 1;
            CVT_ST4(As[nxt], lrow, lseg, a0); CVT_ST4(As[nxt], lrow + 64, lseg, a1);
            CVT_ST4(Bs[nxt], lrow, lseg, b0); CVT_ST4(Bs[nxt], lrow + 64, lseg, b1);
        }
        __syncthreads();
    }
}

// =========================================================================
// NN core: C tile of A[M,K](row,K-contig) x B[K,N](row,N-contig)
// =========================================================================
__device__ __forceinline__ void mma_nn_core(
    const float* __restrict__ A, int lda,
    const float* __restrict__ B, int ldb,
    int m0, int n0, int K, float (&acc)[4][4][4])
{
    __shared__ unsigned As[2][128][20];
    __shared__ unsigned Bs[2][16][136];
    const int t = threadIdx.x;
    const int lane = t & 31, warp = t >> 5;
    const int g = lane >> 2, t4 = lane & 3;
    const int wr = (warp & 1) * 64, wc = (warp >> 1) * 32;
    const int lrow = t >> 2, lseg = (t & 3) * 4;
    const int kr = t >> 5, nseg = (t & 31) * 4;

    const float* Ab = A + (size_t)(m0 + lrow) * lda + lseg;
    const float* Bb = B + (size_t)kr * ldb + n0 + nseg;

    {
        float4 a0 = *(const float4*)(Ab);
        float4 a1 = *(const float4*)(Ab + (size_t)64 * lda);
        float4 b0 = *(const float4*)(Bb);
        float4 b1 = *(const float4*)(Bb + (size_t)8 * ldb);
        CVT_ST4(As[0], lrow, lseg, a0); CVT_ST4(As[0], lrow + 64, lseg, a1);
        CVT_ST4(Bs[0], kr, nseg, b0);   CVT_ST4(Bs[0], kr + 8, nseg, b1);
    }
    __syncthreads();
    const int KT = K >> 4;
    for (int kt = 0; kt < KT; kt++) {
        const int cur = kt & 1;
        float4 a0, a1, b0, b1;
        const bool pf = (kt + 1 < KT);
        if (pf) {
            const float* Ap = Ab + (kt + 1) * 16;
            const float* Bp = Bb + (size_t)(kt + 1) * 16 * ldb;
            a0 = *(const float4*)Ap; a1 = *(const float4*)(Ap + (size_t)64 * lda);
            b0 = *(const float4*)Bp; b1 = *(const float4*)(Bp + (size_t)8 * ldb);
        }
#pragma unroll
        for (int ks = 0; ks < 2; ks++) {
            const int k = ks * 8;
            unsigned af[4][4], bf[4][2];
#pragma unroll
            for (int mt = 0; mt < 4; mt++) {
                const int r = wr + mt * 16;
                af[mt][0] = As[cur][r + g][k + t4];
                af[mt][1] = As[cur][r + g + 8][k + t4];
                af[mt][2] = As[cur][r + g][k + t4 + 4];
                af[mt][3] = As[cur][r + g + 8][k + t4 + 4];
            }
#pragma unroll
            for (int nt = 0; nt < 4; nt++) {
                const int c = wc + nt * 8 + g;
                bf[nt][0] = Bs[cur][k + t4][c];
                bf[nt][1] = Bs[cur][k + t4 + 4][c];
            }
#pragma unroll
            for (int mt = 0; mt < 4; mt++)
#pragma unroll
                for (int nt = 0; nt < 4; nt++)
                    mma8(acc[mt][nt], af[mt], bf[nt]);
        }
        if (pf) {
            const int nxt = cur ^ 1;
            CVT_ST4(As[nxt], lrow, lseg, a0); CVT_ST4(As[nxt], lrow + 64, lseg, a1);
            CVT_ST4(Bs[nxt], kr, nseg, b0);   CVT_ST4(Bs[nxt], kr + 8, nseg, b1);
        }
        __syncthreads();
    }
}

// =========================================================================
// TN core: C[m,n] = sum_k A[k,m] * B[k,n], both N-contiguous (ld = 512)
// =========================================================================
__device__ __forceinline__ void mma_tn_core(
    const float* __restrict__ A, const float* __restrict__ B, int ld,
    int m0, int n0, int K, float (&acc)[4][4][4])
{
    __shared__ unsigned As[2][16][136];
    __shared__ unsigned Bs[2][16][136];
    const int t = threadIdx.x;
    const int lane = t & 31, warp = t >> 5;
    const int g = lane >> 2, t4 = lane & 3;
    const int wr = (warp & 1) * 64, wc = (warp >> 1) * 32;
    const int kr = t >> 5, nseg = (t & 31) * 4;

    const float* Ab = A + (size_t)kr * ld + m0 + nseg;
    const float* Bb = B + (size_t)kr * ld + n0 + nseg;

    {
        float4 a0 = *(const float4*)(Ab);
        float4 a1 = *(const float4*)(Ab + (size_t)8 * ld);
        float4 b0 = *(const float4*)(Bb);
        float4 b1 = *(const float4*)(Bb + (size_t)8 * ld);
        CVT_ST4(As[0], kr, nseg, a0); CVT_ST4(As[0], kr + 8, nseg, a1);
        CVT_ST4(Bs[0], kr, nseg, b0); CVT_ST4(Bs[0], kr + 8, nseg, b1);
    }
    __syncthreads();
    const int KT = K >> 4;
    for (int kt = 0; kt < KT; kt++) {
        const int cur = kt & 1;
        float4 a0, a1, b0, b1;
        const bool pf = (kt + 1 < KT);
        if (pf) {
            const float* Ap = Ab + (size_t)(kt + 1) * 16 * ld;
            const float* Bp = Bb + (size_t)(kt + 1) * 16 * ld;
            a0 = *(const float4*)Ap; a1 = *(const float4*)(Ap + (size_t)8 * ld);
            b0 = *(const float4*)Bp; b1 = *(const float4*)(Bp + (size_t)8 * ld);
        }
#pragma unroll
        for (int ks = 0; ks < 2; ks++) {
            const int k = ks * 8;
            unsigned af[4][4], bf[4][2];
#pragma unroll
            for (int mt = 0; mt < 4; mt++) {
                const int r = wr + mt * 16;
                af[mt][0] = As[cur][k + t4][r + g];
                af[mt][1] = As[cur][k + t4][r + g + 8];
                af[mt][2] = As[cur][k + t4 + 4][r + g];
                af[mt][3] = As[cur][k + t4 + 4][r + g + 8];
            }
#pragma unroll
            for (int nt = 0; nt < 4; nt++) {
                const int c = wc + nt * 8 + g;
                bf[nt][0] = Bs[cur][k + t4][c];
                bf[nt][1] = Bs[cur][k + t4 + 4][c];
            }
#pragma unroll
            for (int mt = 0; mt < 4; mt++)
#pragma unroll
                for (int nt = 0; nt < 4; nt++)
                    mma8(acc[mt][nt], af[mt], bf[nt]);
        }
        if (pf) {
            const int nxt = cur ^ 1;
            CVT_ST4(As[nxt], kr, nseg, a0); CVT_ST4(As[nxt], kr + 8, nseg, a1);
            CVT_ST4(Bs[nxt], kr, nseg, b0); CVT_ST4(Bs[nxt], kr + 8, nseg, b1);
        }
        __syncthreads();
    }
}

#define ZERO_ACC(acc)                              \
    _Pragma("unroll")                              \
    for (int mt = 0; mt < 4; mt++)                 \
        _Pragma("unroll")                          \
        for (int nt = 0; nt < 4; nt++)             \
            _Pragma("unroll")                      \
            for (int e = 0; e < 4; e++) acc[mt][nt][e] = 0.0f;

// accumulator element e -> (row = g + (e>>1)*8, col = 2*t4 + (e&1))

// ---------------- init ----------------
__global__ void k_init() {
    int i = blockIdx.x * blockDim.x + threadIdx.x;
    if (i < N_HID * N_HID) g_G[i] = 0.0f;
    if (i == 0) { g_feat_loss = 0.0f; g_node_loss = 0.0f; }
}

// ---------------- fts = seq @ W^T (NT) ----------------
__global__ __launch_bounds__(256) void k_gemm_fts(
    const float* __restrict__ seq1, const float* __restrict__ seq2,
    const float* __restrict__ W1,   const float* __restrict__ W2)
{
    const int z = blockIdx.z;
    const float* A = (z & 2) ? seq2 : seq1;
    const float* B = (z & 1) ? W2 : W1;
    float* __restrict__ C = g_fts[z];
    const int m0 = blockIdx.y * 128, n0 = blockIdx.x * 128;

    float acc[4][4][4];
    ZERO_ACC(acc);
    mma_nt_core(A, N_INF, B, N_INF, m0, n0, N_INF, acc);

    const int lane = threadIdx.x & 31, warp = threadIdx.x >> 5;
    const int g = lane >> 2, t4 = lane & 3;
    const int wr = (warp & 1) * 64, wc = (warp >> 1) * 32;
#pragma unroll
    for (int mt = 0; mt < 4; mt++)
#pragma unroll
        for (int nt = 0; nt < 4; nt++)
#pragma unroll
            for (int e = 0; e < 4; e++) {
                int row = m0 + wr + mt * 16 + g + (e >> 1) * 8;
                int col = n0 + wc + nt * 8 + 2 * t4 + (e & 1);
                C[(size_t)row * N_HID + col] = acc[mt][nt][e];
            }
}

// ---------------- h = prelu(A @ fts + b) (NN) ----------------
__global__ __launch_bounds__(256) void k_gemm_prop(
    const float* __restrict__ adj, const float* __restrict__ diff,
    const float* __restrict__ b1,  const float* __restrict__ b2,
    const float* __restrict__ a1,  const float* __restrict__ a2)
{
    const int z = blockIdx.z;
    const float* A = (z & 1) ? diff : adj;
    const float* B = g_fts[z];
    const float* bias = (z & 1) ? b2 : b1;
    const float slope = (z & 1) ? a2[0] : a1[0];
    float* __restrict__ C = g_h[z];
    const int m0 = blockIdx.y * 128, n0 = blockIdx.x * 128;

    float acc[4][4][4];
    ZERO_ACC(acc);
    mma_nn_core(A, N_NODES, B, N_HID, m0, n0, N_NODES, acc);

    const int lane = threadIdx.x & 31, warp = threadIdx.x >> 5;
    const int g = lane >> 2, t4 = lane & 3;
    const int wr = (warp & 1) * 64, wc = (warp >> 1) * 32;
#pragma unroll
    for (int mt = 0; mt < 4; mt++)
#pragma unroll
        for (int nt = 0; nt < 4; nt++)
#pragma unroll
            for (int e = 0; e < 4; e++) {
                int row = m0 + wr + mt * 16 + g + (e >> 1) * 8;
                int col = n0 + wc + nt * 8 + 2 * t4 + (e & 1);
                float v = acc[mt][nt][e] + bias[col];
                v = (v >= 0.0f) ? v : slope * v;
                C[(size_t)row * N_HID + col] = v;
            }
}

// ---------------- Z = h1 + h2, row inv-norms ----------------
__global__ void k_compute_Z() {
    const int r = blockIdx.x;
    const int c = threadIdx.x;
    float z = g_h[0][(size_t)r * N_HID + c] + g_h[1][(size_t)r * N_HID + c];
    g_Z[(size_t)r * N_HID + c] = z;
    __shared__ float red[512];
    red[c] = z * z;
    __syncthreads();
    for (int s = 256; s > 0; s >>= 1) {
        if (c < s) red[c] += red[c + s];
        __syncthreads();
    }
    if (c == 0) g_rninv[r] = 1.0f / fmaxf(sqrtf(red[0]), 1e-12f);
}

// ---------------- column reductions ----------------
__global__ void k_col_reduce() {
    const int mode = blockIdx.y;
    const int tx = threadIdx.x & 31;
    const int ty = threadIdx.x >> 5;
    const int col = blockIdx.x * 32 + tx;
    const float* __restrict__ src = (mode == 0) ? g_h[0] : (mode == 1) ? g_h[1] : g_Z;
    float s = 0.0f;
    for (int r = ty; r < N_NODES; r += 8) {
        float v = src[(size_t)r * N_HID + col];
        s += (mode == 2) ? v * v : v;
    }
    __shared__ float sm[8][32];
    sm[ty][tx] = s;
    __syncthreads();
    if (ty == 0) {
        float tot = 0.0f;
#pragma unroll
        for (int k = 0; k < 8; k++) tot += sm[k][tx];
        if (mode == 2) g_cninv[col] = 1.0f / fmaxf(sqrtf(tot), 1e-12f);
        else g_csum[mode][col] = tot;
    }
}

// ---------------- u = Wd @ sigmoid(colmean) ----------------
__global__ void k_compute_u(const float* __restrict__ Wd) {
    __shared__ float c1s[512], c2s[512];
    const int h = threadIdx.x;
    c1s[h] = 1.0f / (1.0f + expf(-g_csum[0][h] * (1.0f / 4096.0f)));
    c2s[h] = 1.0f / (1.0f + expf(-g_csum[1][h] * (1.0f / 4096.0f)));
    __syncthreads();
    float u1 = 0.0f, u2 = 0.0f;
    const float4* Wrow = reinterpret_cast<const float4*>(Wd + (size_t)h * N_HID);
#pragma unroll 4
    for (int k4 = 0; k4 < 128; k4++) {
        float4 w = Wrow[k4];
        int k = k4 * 4;
        u1 += w.x * c1s[k] + w.y * c1s[k + 1] + w.z * c1s[k + 2] + w.w * c1s[k + 3];
        u2 += w.x * c2s[k] + w.y * c2s[k + 1] + w.z * c2s[k + 2] + w.w * c2s[k + 3];
    }
    g_u[0][h] = u1;
    g_u[1][h] = u2;
}

// ---------------- ret ----------------
__global__ void k_ret(const float* __restrict__ bd, float* __restrict__ out) {
    const int q = blockIdx.y;
    const int n = blockIdx.x * 8 + (threadIdx.x >> 5);
    const int lane = threadIdx.x & 31;
    const float* __restrict__ h = (q == 0) ? g_h[1] : (q == 1) ? g_h[0]
                                : (q == 2) ? g_h[3] : g_h[2];
    const float* __restrict__ u = (q == 0 || q == 2) ? g_u[0] : g_u[1];
    float s = 0.0f;
    for (int k = lane; k < N_HID; k += 32)
        s += h[(size_t)n * N_HID + k] * u[k];
#pragma unroll
    for (int o = 16; o > 0; o >>= 1) s += __shfl_down_sync(0xFFFFFFFFu, s, o);
    if (lane == 0) out[q * N_NODES + n] = s + bd[0];
}

// ---------------- G = Z^T Z (TN, split-K) ----------------
__global__ __launch_bounds__(256) void k_gemm_G() {
    const int m0 = blockIdx.y * 128, n0 = blockIdx.x * 128;
    const float* Zk = g_Z + (size_t)blockIdx.z * 512 * N_HID;

    float acc[4][4][4];
    ZERO_ACC(acc);
    mma_tn_core(Zk, Zk, N_HID, m0, n0, 512, acc);

    const int lane = threadIdx.x & 31, warp = threadIdx.x >> 5;
    const int g = lane >> 2, t4 = lane & 3;
    const int wr = (warp & 1) * 64, wc = (warp >> 1) * 32;
#pragma unroll
    for (int mt = 0; mt < 4; mt++)
#pragma unroll
        for (int nt = 0; nt < 4; nt++)
#pragma unroll
            for (int e = 0; e < 4; e++) {
                int row = m0 + wr + mt * 16 + g + (e >> 1) * 8;
                int col = n0 + wc + nt * 8 + 2 * t4 + (e & 1);
                atomicAdd(&g_G[(size_t)row * N_HID + col], acc[mt][nt][e]);
            }
}

// ---------------- feat loss ----------------
__global__ void k_feat_loss(const int* __restrict__ feat_index) {
    const int h = blockIdx.x;
    const int k = threadIdx.x;
    __shared__ float sv[512];
    float feat = g_G[(size_t)h * N_HID + k] * g_cninv[h] * g_cninv[k];
    sv[k] = feat * feat;
    __syncthreads();
    const float diag = sv[h];
    __syncthreads();
    for (int kk = 2; kk <= 512; kk <<= 1) {
        for (int j = kk >> 1; j > 0; j >>= 1) {
            int i = k;
            int ixj = i ^ j;
            if (ixj > i) {
                float a = sv[i], b = sv[ixj];
                bool up = ((i & kk) == 0);
                if ((a > b) == up) { sv[i] = b; sv[ixj] = a; }
            }
            __syncthreads();
        }
    }
    if (k == 0) {
        float neg = 0.0f;
#pragma unroll
        for (int s = 0; s < N_S; s++) neg += expf(2.0f * sv[feat_index[s]]);
        float pos = expf(2.0f * diag);
        atomicAdd(&g_feat_loss, (logf(neg) - logf(pos)) * (1.0f / 512.0f));
    }
}

// ---------------- node^2 = (Zn Zn^T)^2 (NT) ----------------
__global__ __launch_bounds__(256) void k_gemm_node() {
    const int m0 = blockIdx.y * 128, n0 = blockIdx.x * 128;

    float acc[4][4][4];
    ZERO_ACC(acc);
    mma_nt_core(g_Z, N_HID, g_Z, N_HID, m0, n0, N_HID, acc);

    const int lane = threadIdx.x & 31, warp = threadIdx.x >> 5;
    const int g = lane >> 2, t4 = lane & 3;
    const int wr = (warp & 1) * 64, wc = (warp >> 1) * 32;
#pragma unroll
    for (int mt = 0; mt < 4; mt++)
#pragma unroll
        for (int nt = 0; nt < 4; nt++)
#pragma unroll
            for (int e = 0; e < 4; e++) {
                int row = m0 + wr + mt * 16 + g + (e >> 1) * 8;
                int col = n0 + wc + nt * 8 + 2 * t4 + (e & 1);
                float x = acc[mt][nt][e] * g_rninv[row] * g_rninv[col];
                g_node_sq[(size_t)row * N_NODES + col] = x * x;
            }
}

// ---------------- node loss ----------------
__global__ void k_node_row(const float* __restrict__ adj_label,
                           const int* __restrict__ node_index) {
    const int i = blockIdx.x;
    const int tid = threadIdx.x;
    __shared__ float sv[4096];
    __shared__ float red[512];
    const float* __restrict__ trow = g_node_sq + (size_t)i * N_NODES;
    const float* __restrict__ lrow = adj_label + (size_t)i * N_NODES;
    float pos = 0.0f;
    for (int j = tid; j < N_NODES; j += 512) {
        float t = trow[j];
        sv[j] = t;
        pos += expf(2.0f * t) * lrow[j];
    }
    red[tid] = pos;
    __syncthreads();
    for (int s = 256; s > 0; s >>= 1) {
        if (tid < s) red[tid] += red[tid + s];
        __syncthreads();
    }
    const float posSum = red[0];
    __syncthreads();
    for (int kk = 2; kk <= 4096; kk <<= 1) {
        for (int j = kk >> 1; j > 0; j >>= 1) {
            for (int idx = tid; idx < 4096; idx += 512) {
                int ixj = idx ^ j;
                if (ixj > idx) {
                    float a = sv[idx], b = sv[ixj];
                    bool up = ((idx & kk) == 0);
                    if ((a > b) == up) { sv[idx] = b; sv[ixj] = a; }
                }
            }
            __syncthreads();
        }
    }
    if (tid == 0) {
        float neg = 0.0f;
#pragma unroll
        for (int s = 0; s < N_S; s++) neg += expf(2.0f * sv[node_index[s]]);
        atomicAdd(&g_node_loss, (logf(neg) - logf(posSum)) * (1.0f / 4096.0f));
    }
}

// ---------------- finalize ----------------
__global__ void k_finalize(float* __restrict__ out) {
    out[4 * N_NODES + 0] = g_feat_loss;
    out[4 * N_NODES + 1] = g_node_loss;
}

// ---------------- launch ----------------
extern "C" void kernel_launch(void* const* d_in, const int* in_sizes, int n_in,
                              void* d_out, int out_size) {
    const float* seq1      = (const float*)d_in[0];
    const float* seq2      = (const float*)d_in[1];
    const float* adj       = (const float*)d_in[2];
    const float* diff      = (const float*)d_in[3];
    const float* adj_label = (const float*)d_in[4];
    const int*   feat_idx  = (const int*)d_in[5];
    const int*   node_idx  = (const int*)d_in[6];
    const float* W1        = (const float*)d_in[7];
    const float* b1        = (const float*)d_in[8];
    const float* a1        = (const float*)d_in[9];
    const float* W2        = (const float*)d_in[10];
    const float* b2        = (const float*)d_in[11];
    const float* a2        = (const float*)d_in[12];
    const float* Wd        = (const float*)d_in[13];
    const float* bd        = (const float*)d_in[14];
    float* out = (float*)d_out;

    k_init<<<(N_HID * N_HID + 255) / 256, 256>>>();
    k_gemm_fts<<<dim3(4, 32, 4), 256>>>(seq1, seq2, W1, W2);
    k_gemm_prop<<<dim3(4, 32, 4), 256>>>(adj, diff, b1, b2, a1, a2);
    k_compute_Z<<<N_NODES, 512>>>();
    k_col_reduce<<<dim3(16, 3), 256>>>();
    k_compute_u<<<1, 512>>>(Wd);
    k_ret<<<dim3(512, 4), 256>>>(bd, out);
    k_gemm_G<<<dim3(4, 4, 8), 256>>>();
    k_feat_loss<<<512, 512>>>(feat_idx);
    k_gemm_node<<<dim3(32, 32), 256>>>();
    k_node_row<<<N_NODES, 512>>>(adj_label, node_idx);
    k_finalize<<<1, 1>>>(out);
}

// round 3
// speedup vs baseline: 2.3080x; 1.1073x over previous
#include <cuda_runtime.h>
#include <math.h>
#include <stdint.h>

#define N_NODES 4096
#define N_HID   512
#define N_INF   512
#define N_S     10

// ---------------- scratch ----------------
__device__ float g_adjc[(size_t)N_NODES * N_NODES];
__device__ float g_diffc[(size_t)N_NODES * N_NODES];
__device__ float g_seqc[2][N_NODES * N_INF];
__device__ float g_Wc[2][N_HID * N_INF];
__device__ float g_fts[4][N_HID * N_NODES];          // ftsT: [h][node], tf32-rounded
__device__ float g_h[4][N_NODES * N_HID];            // h1..h4
__device__ float g_Z[N_NODES * N_HID];               // h1+h2, tf32-rounded
__device__ float g_G[N_HID * N_HID];
__device__ float g_node_sq[(size_t)N_NODES * N_NODES];
__device__ float g_csum[2][N_HID];
__device__ float g_u[2][N_HID];
__device__ float g_rninv[N_NODES];
__device__ float g_cninv[N_HID];
__device__ float g_feat_loss;
__device__ float g_node_loss;

// ---------------- helpers ----------------
__device__ __forceinline__ unsigned f2tf32(float x) {
    unsigned r;
    asm("cvt.rna.tf32.f32 %0, %1;" : "=r"(r) : "f"(x));
    return r;
}

__device__ __forceinline__ void mma8(float (&c)[4], const unsigned (&a)[4],
                                     const unsigned (&b)[2]) {
    asm volatile(
        "mma.sync.aligned.m16n8k8.row.col.f32.tf32.tf32.f32 "
        "{%0,%1,%2,%3}, {%4,%5,%6,%7}, {%8,%9}, {%0,%1,%2,%3};\n"
        : "+f"(c[0]), "+f"(c[1]), "+f"(c[2]), "+f"(c[3])
        : "r"(a[0]), "r"(a[1]), "r"(a[2]), "r"(a[3]), "r"(b[0]), "r"(b[1]));
}

__device__ __forceinline__ void ldsm_x4(unsigned (&r)[4], uint32_t addr) {
    asm volatile("ldmatrix.sync.aligned.m8n8.x4.shared.b16 {%0,%1,%2,%3}, [%4];"
                 : "=r"(r[0]), "=r"(r[1]), "=r"(r[2]), "=r"(r[3]) : "r"(addr));
}

__device__ __forceinline__ void cpa16(uint32_t smem, const void* gmem) {
    asm volatile("cp.async.cg.shared.global [%0], [%1], 16;"
                 :: "r"(smem), "l"(gmem));
}

// =========================================================================
// NT pipelined core: C[128,256] = A[M,K] x B[N,K]^T, operands pre-tf32.
// 256 threads, warp grid 2(M) x 4(N), warp tile 64x64.
// Dynamic smem: A 3 stages x 128x16 fl + B 3 stages x 256x16 fl = 72KB.
// Swizzle: 16B chunk (r, c4) at byte r*64 + ((c4 ^ ((r>>1)&3))<<4).
// =========================================================================
#define SMEM_A_STAGE 8192
#define SMEM_B_STAGE 16384
#define SMEM_B_BASE  (3 * SMEM_A_STAGE)
#define SMEM_TOTAL_G (SMEM_B_BASE + 3 * SMEM_B_STAGE)

__device__ __forceinline__ void nt_core(
    const float* __restrict__ A, int lda,
    const float* __restrict__ B, int ldb,
    int m0, int n0, int K, float (&acc)[4][8][4])
{
    extern __shared__ char smem[];
    const uint32_t sbase = (uint32_t)__cvta_generic_to_shared(smem);

    const int t = threadIdx.x;
    const int lane = t & 31, warp = t >> 5;
    const int wr = (warp & 1) * 64, wc = (warp >> 1) * 64;
    const int q = lane >> 3, rowin = lane & 7;
    const int qlo = q & 1, qhi = q >> 1;

    // per-lane ldmatrix row precompute
    uint32_t aR64[4], aSw[4], bR64[4], bSw[4];
#pragma unroll
    for (int mt = 0; mt < 4; mt++) {
        int r = wr + mt * 16 + qlo * 8 + rowin;
        aR64[mt] = r * 64; aSw[mt] = (r >> 1) & 3;
    }
#pragma unroll
    for (int np = 0; np < 4; np++) {
        int r = wc + (np * 2 + qhi) * 8 + rowin;
        bR64[np] = r * 64; bSw[np] = (r >> 1) & 3;
    }

    const int KT = K >> 4;

    // issue stage
    auto issue = [&](int kt, int buf) {
        const uint32_t sa = sbase + buf * SMEM_A_STAGE;
        const uint32_t sb = sbase + SMEM_B_BASE + buf * SMEM_B_STAGE;
#pragma unroll
        for (int i = 0; i < 2; i++) {
            int chunk = t + i * 256;
            int r = chunk >> 2, c4 = chunk & 3;
            uint32_t dst = sa + r * 64 + (((unsigned)(c4 ^ ((r >> 1) & 3))) << 4);
            cpa16(dst, A + (size_t)(m0 + r) * lda + kt * 16 + c4 * 4);
        }
#pragma unroll
        for (int i = 0; i < 4; i++) {
            int chunk = t + i * 256;
            int r = chunk >> 2, c4 = chunk & 3;
            uint32_t dst = sb + r * 64 + (((unsigned)(c4 ^ ((r >> 1) & 3))) << 4);
            cpa16(dst, B + (size_t)(n0 + r) * ldb + kt * 16 + c4 * 4);
        }
        asm volatile("cp.async.commit_group;");
    };

    issue(0, 0);
    issue(1, 1);

    for (int kt = 0; kt < KT; kt++) {
        if (kt + 1 < KT) { asm volatile("cp.async.wait_group 1;"); }
        else             { asm volatile("cp.async.wait_group 0;"); }
        __syncthreads();
        if (kt + 2 < KT) issue(kt + 2, (kt + 2) % 3);

        const int buf = kt % 3;
        const uint32_t sa = sbase + buf * SMEM_A_STAGE;
        const uint32_t sb = sbase + SMEM_B_BASE + buf * SMEM_B_STAGE;
#pragma unroll
        for (int ks = 0; ks < 2; ks++) {
            unsigned af[4][4], bf[8][2];
#pragma unroll
            for (int mt = 0; mt < 4; mt++) {
                uint32_t c4 = ks * 2 + qhi;
                ldsm_x4(af[mt], sa + aR64[mt] + ((c4 ^ aSw[mt]) << 4));
            }
#pragma unroll
            for (int np = 0; np < 4; np++) {
                unsigned r4[4];
                uint32_t c4 = ks * 2 + qlo;
                ldsm_x4(r4, sb + bR64[np] + ((c4 ^ bSw[np]) << 4));
                bf[np * 2 + 0][0] = r4[0]; bf[np * 2 + 0][1] = r4[1];
                bf[np * 2 + 1][0] = r4[2]; bf[np * 2 + 1][1] = r4[3];
            }
#pragma unroll
            for (int mt = 0; mt < 4; mt++)
#pragma unroll
                for (int nt = 0; nt < 8; nt++)
                    mma8(acc[mt][nt], af[mt], bf[nt]);
        }
        __syncthreads();
    }
}

#define ZERO_ACC8(acc)                             \
    _Pragma("unroll")                              \
    for (int mt = 0; mt < 4; mt++)                 \
        _Pragma("unroll")                          \
        for (int nt = 0; nt < 8; nt++)             \
            _Pragma("unroll")                      \
            for (int e = 0; e < 4; e++) acc[mt][nt][e] = 0.0f;

// ---------------- init ----------------
__global__ void k_init() {
    int i = blockIdx.x * blockDim.x + threadIdx.x;
    if (i < N_HID * N_HID) g_G[i] = 0.0f;
    if (i == 0) { g_feat_loss = 0.0f; g_node_loss = 0.0f; }
}

// ---------------- tf32 pre-convert ----------------
__global__ void k_cvt(const float4* __restrict__ src, float4* __restrict__ dst, int n4) {
    int i = blockIdx.x * blockDim.x + threadIdx.x;
    if (i < n4) {
        float4 v = src[i];
        v.x = __uint_as_float(f2tf32(v.x));
        v.y = __uint_as_float(f2tf32(v.y));
        v.z = __uint_as_float(f2tf32(v.z));
        v.w = __uint_as_float(f2tf32(v.w));
        dst[i] = v;
    }
}

// ---------------- ftsT[z] = W[z] x seq[z]^T : M=512, N=4096, K=512 ----------------
__global__ __launch_bounds__(256) void k_gemm_ftsT() {
    const int z = blockIdx.z;
    const float* A = g_Wc[z & 1];
    const float* B = g_seqc[z >> 1];
    float* __restrict__ C = g_fts[z];
    const int m0 = blockIdx.y * 128, n0 = blockIdx.x * 256;

    float acc[4][8][4];
    ZERO_ACC8(acc);
    nt_core(A, N_INF, B, N_INF, m0, n0, N_INF, acc);

    const int lane = threadIdx.x & 31, warp = threadIdx.x >> 5;
    const int g = lane >> 2, t4 = lane & 3;
    const int wr = (warp & 1) * 64, wc = (warp >> 1) * 64;
#pragma unroll
    for (int mt = 0; mt < 4; mt++)
#pragma unroll
        for (int nt = 0; nt < 8; nt++)
#pragma unroll
            for (int e = 0; e < 4; e++) {
                int row = m0 + wr + mt * 16 + g + (e >> 1) * 8;
                int col = n0 + wc + nt * 8 + 2 * t4 + (e & 1);
                C[(size_t)row * N_NODES + col] = __uint_as_float(f2tf32(acc[mt][nt][e]));
            }
}

// ---------------- h[z] = prelu(adj x ftsT^T + b): M=4096, N=512, K=4096 ------------
__global__ __launch_bounds__(256) void k_gemm_prop(
    const float* __restrict__ b1,  const float* __restrict__ b2,
    const float* __restrict__ a1,  const float* __restrict__ a2)
{
    const int z = blockIdx.z;
    const float* A = (z & 1) ? g_diffc : g_adjc;
    const float* B = g_fts[z];
    const float* bias = (z & 1) ? b2 : b1;
    const float slope = (z & 1) ? a2[0] : a1[0];
    float* __restrict__ C = g_h[z];
    const int m0 = blockIdx.y * 128, n0 = blockIdx.x * 256;

    float acc[4][8][4];
    ZERO_ACC8(acc);
    nt_core(A, N_NODES, B, N_NODES, m0, n0, N_NODES, acc);

    const int lane = threadIdx.x & 31, warp = threadIdx.x >> 5;
    const int g = lane >> 2, t4 = lane & 3;
    const int wr = (warp & 1) * 64, wc = (warp >> 1) * 64;
#pragma unroll
    for (int mt = 0; mt < 4; mt++)
#pragma unroll
        for (int nt = 0; nt < 8; nt++)
#pragma unroll
            for (int e = 0; e < 4; e++) {
                int row = m0 + wr + mt * 16 + g + (e >> 1) * 8;
                int col = n0 + wc + nt * 8 + 2 * t4 + (e & 1);
                float v = acc[mt][nt][e] + bias[col];
                v = (v >= 0.0f) ? v : slope * v;
                C[(size_t)row * N_HID + col] = v;
            }
}

// ---------------- node_sq = (Zn Zn^T)^2: M=N=4096, K=512 ----------------
__global__ __launch_bounds__(256) void k_gemm_node() {
    const int m0 = blockIdx.y * 128, n0 = blockIdx.x * 256;

    float acc[4][8][4];
    ZERO_ACC8(acc);
    nt_core(g_Z, N_HID, g_Z, N_HID, m0, n0, N_HID, acc);

    const int lane = threadIdx.x & 31, warp = threadIdx.x >> 5;
    const int g = lane >> 2, t4 = lane & 3;
    const int wr = (warp & 1) * 64, wc = (warp >> 1) * 64;
#pragma unroll
    for (int mt = 0; mt < 4; mt++) {
        int row = m0 + wr + mt * 16 + g;  // + (e>>1)*8
        float ri0 = g_rninv[row], ri1 = g_rninv[row + 8];
#pragma unroll
        for (int nt = 0; nt < 8; nt++)
#pragma unroll
            for (int e = 0; e < 4; e++) {
                int r = row + (e >> 1) * 8;
                int col = n0 + wc + nt * 8 + 2 * t4 + (e & 1);
                float x = acc[mt][nt][e] * ((e >> 1) ? ri1 : ri0) * g_rninv[col];
                g_node_sq[(size_t)r * N_NODES + col] = x * x;
            }
    }
}

// ---------------- Z = h1 + h2 (tf32-rounded), row inv-norms ----------------
__global__ void k_compute_Z() {
    const int r = blockIdx.x;
    const int c = threadIdx.x;
    float z = g_h[0][(size_t)r * N_HID + c] + g_h[1][(size_t)r * N_HID + c];
    float zr = __uint_as_float(f2tf32(z));
    g_Z[(size_t)r * N_HID + c] = zr;
    __shared__ float red[512];
    red[c] = zr * zr;
    __syncthreads();
    for (int s = 256; s > 0; s >>= 1) {
        if (c < s) red[c] += red[c + s];
        __syncthreads();
    }
    if (c == 0) g_rninv[r] = 1.0f / fmaxf(sqrtf(red[0]), 1e-12f);
}

// ---------------- column reductions ----------------
__global__ void k_col_reduce() {
    const int mode = blockIdx.y;
    const int tx = threadIdx.x & 31;
    const int ty = threadIdx.x >> 5;
    const int col = blockIdx.x * 32 + tx;
    const float* __restrict__ src = (mode == 0) ? g_h[0] : (mode == 1) ? g_h[1] : g_Z;
    float s = 0.0f;
    for (int r = ty; r < N_NODES; r += 8) {
        float v = src[(size_t)r * N_HID + col];
        s += (mode == 2) ? v * v : v;
    }
    __shared__ float sm[8][32];
    sm[ty][tx] = s;
    __syncthreads();
    if (ty == 0) {
        float tot = 0.0f;
#pragma unroll
        for (int k = 0; k < 8; k++) tot += sm[k][tx];
        if (mode == 2) g_cninv[col] = 1.0f / fmaxf(sqrtf(tot), 1e-12f);
        else g_csum[mode][col] = tot;
    }
}

// ---------------- u = Wd @ sigmoid(colmean) ----------------
__global__ void k_compute_u(const float* __restrict__ Wd) {
    __shared__ float c1s[512], c2s[512];
    const int h = threadIdx.x;
    c1s[h] = 1.0f / (1.0f + expf(-g_csum[0][h] * (1.0f / 4096.0f)));
    c2s[h] = 1.0f / (1.0f + expf(-g_csum[1][h] * (1.0f / 4096.0f)));
    __syncthreads();
    float u1 = 0.0f, u2 = 0.0f;
    const float4* Wrow = reinterpret_cast<const float4*>(Wd + (size_t)h * N_HID);
#pragma unroll 4
    for (int k4 = 0; k4 < 128; k4++) {
        float4 w = Wrow[k4];
        int k = k4 * 4;
        u1 += w.x * c1s[k] + w.y * c1s[k + 1] + w.z * c1s[k + 2] + w.w * c1s[k + 3];
        u2 += w.x * c2s[k] + w.y * c2s[k + 1] + w.z * c2s[k + 2] + w.w * c2s[k + 3];
    }
    g_u[0][h] = u1;
    g_u[1][h] = u2;
}

// ---------------- ret ----------------
__global__ void k_ret(const float* __restrict__ bd, float* __restrict__ out) {
    const int q = blockIdx.y;
    const int n = blockIdx.x * 8 + (threadIdx.x >> 5);
    const int lane = threadIdx.x & 31;
    const float* __restrict__ h = (q == 0) ? g_h[1] : (q == 1) ? g_h[0]
                                : (q == 2) ? g_h[3] : g_h[2];
    const float* __restrict__ u = (q == 0 || q == 2) ? g_u[0] : g_u[1];
    float s = 0.0f;
    for (int k = lane; k < N_HID; k += 32)
        s += h[(size_t)n * N_HID + k] * u[k];
#pragma unroll
    for (int o = 16; o > 0; o >>= 1) s += __shfl_down_sync(0xFFFFFFFFu, s, o);
    if (lane == 0) out[q * N_NODES + n] = s + bd[0];
}

// =========================================================================
// TN core (kept from R2) for G = Z^T Z, split-K, small
// =========================================================================
__device__ __forceinline__ void mma_tn_core(
    const float* __restrict__ A, const float* __restrict__ B, int ld,
    int m0, int n0, int K, float (&acc)[4][4][4])
{
    __shared__ unsigned As[2][16][136];
    __shared__ unsigned Bs[2][16][136];
    const int t = threadIdx.x;
    const int lane = t & 31, warp = t >> 5;
    const int g = lane >> 2, t4 = lane & 3;
    const int wr = (warp & 1) * 64, wc = (warp >> 1) * 32;
    const int kr = t >> 5, nseg = (t & 31) * 4;

    const float* Ab = A + (size_t)kr * ld + m0 + nseg;
    const float* Bb = B + (size_t)kr * ld + n0 + nseg;

#define CVT_ST4(dst, row, seg, v)                        \
    dst[row][(seg) + 0] = f2tf32(v.x);                   \
    dst[row][(seg) + 1] = f2tf32(v.y);                   \
    dst[row][(seg) + 2] = f2tf32(v.z);                   \
    dst[row][(seg) + 3] = f2tf32(v.w);

    {
        float4 a0 = *(const float4*)(Ab);
        float4 a1 = *(const float4*)(Ab + (size_t)8 * ld);
        float4 b0 = *(const float4*)(Bb);
        float4 b1 = *(const float4*)(Bb + (size_t)8 * ld);
        CVT_ST4(As[0], kr, nseg, a0); CVT_ST4(As[0], kr + 8, nseg, a1);
        CVT_ST4(Bs[0], kr, nseg, b0); CVT_ST4(Bs[0], kr + 8, nseg, b1);
    }
    __syncthreads();
    const int KT = K >> 4;
    for (int kt = 0; kt < KT; kt++) {
        const int cur = kt & 1;
        float4 a0, a1, b0, b1;
        const bool pf = (kt + 1 < KT);
        if (pf) {
            const float* Ap = Ab + (size_t)(kt + 1) * 16 * ld;
            const float* Bp = Bb + (size_t)(kt + 1) * 16 * ld;
            a0 = *(const float4*)Ap; a1 = *(const float4*)(Ap + (size_t)8 * ld);
            b0 = *(const float4*)Bp; b1 = *(const float4*)(Bp + (size_t)8 * ld);
        }
#pragma unroll
        for (int ks = 0; ks < 2; ks++) {
            const int k = ks * 8;
            unsigned af[4][4], bf[4][2];
#pragma unroll
            for (int mt = 0; mt < 4; mt++) {
                const int r = wr + mt * 16;
                af[mt][0] = As[cur][k + t4][r + g];
                af[mt][1] = As[cur][k + t4][r + g + 8];
                af[mt][2] = As[cur][k + t4 + 4][r + g];
                af[mt][3] = As[cur][k + t4 + 4][r + g + 8];
            }
#pragma unroll
            for (int nt = 0; nt < 4; nt++) {
                const int c = wc + nt * 8 + g;
                bf[nt][0] = Bs[cur][k + t4][c];
                bf[nt][1] = Bs[cur][k + t4 + 4][c];
            }
#pragma unroll
            for (int mt = 0; mt < 4; mt++)
#pragma unroll
                for (int nt = 0; nt < 4; nt++)
                    mma8(acc[mt][nt], af[mt], bf[nt]);
        }
        if (pf) {
            const int nxt = cur ^ 1;
            CVT_ST4(As[nxt], kr, nseg, a0); CVT_ST4(As[nxt], kr + 8, nseg, a1);
            CVT_ST4(Bs[nxt], kr, nseg, b0); CVT_ST4(Bs[nxt], kr + 8, nseg, b1);
        }
        __syncthreads();
    }
}

__global__ __launch_bounds__(256) void k_gemm_G() {
    const int m0 = blockIdx.y * 128, n0 = blockIdx.x * 128;
    const float* Zk = g_Z + (size_t)blockIdx.z * 512 * N_HID;

    float acc[4][4][4];
#pragma unroll
    for (int mt = 0; mt < 4; mt++)
#pragma unroll
        for (int nt = 0; nt < 4; nt++)
#pragma unroll
            for (int e = 0; e < 4; e++) acc[mt][nt][e] = 0.0f;
    mma_tn_core(Zk, Zk, N_HID, m0, n0, 512, acc);

    const int lane = threadIdx.x & 31, warp = threadIdx.x >> 5;
    const int g = lane >> 2, t4 = lane & 3;
    const int wr = (warp & 1) * 64, wc = (warp >> 1) * 32;
#pragma unroll
    for (int mt = 0; mt < 4; mt++)
#pragma unroll
        for (int nt = 0; nt < 4; nt++)
#pragma unroll
            for (int e = 0; e < 4; e++) {
                int row = m0 + wr + mt * 16 + g + (e >> 1) * 8;
                int col = n0 + wc + nt * 8 + 2 * t4 + (e & 1);
                atomicAdd(&g_G[(size_t)row * N_HID + col], acc[mt][nt][e]);
            }
}

// ---------------- feat loss ----------------
__global__ void k_feat_loss(const int* __restrict__ feat_index) {
    const int h = blockIdx.x;
    const int k = threadIdx.x;
    __shared__ float sv[512];
    float feat = g_G[(size_t)h * N_HID + k] * g_cninv[h] * g_cninv[k];
    sv[k] = feat * feat;
    __syncthreads();
    const float diag = sv[h];
    __syncthreads();
    for (int kk = 2; kk <= 512; kk <<= 1) {
        for (int j = kk >> 1; j > 0; j >>= 1) {
            int i = k;
            int ixj = i ^ j;
            if (ixj > i) {
                float a = sv[i], b = sv[ixj];
                bool up = ((i & kk) == 0);
                if ((a > b) == up) { sv[i] = b; sv[ixj] = a; }
            }
            __syncthreads();
        }
    }
    if (k == 0) {
        float neg = 0.0f;
#pragma unroll
        for (int s = 0; s < N_S; s++) neg += expf(2.0f * sv[feat_index[s]]);
        float pos = expf(2.0f * diag);
        atomicAdd(&g_feat_loss, (logf(neg) - logf(pos)) * (1.0f / 512.0f));
    }
}

// ---------------- node loss ----------------
__global__ void k_node_row(const float* __restrict__ adj_label,
                           const int* __restrict__ node_index) {
    const int i = blockIdx.x;
    const int tid = threadIdx.x;
    __shared__ float sv[4096];
    __shared__ float red[1024];
    const float* __restrict__ trow = g_node_sq + (size_t)i * N_NODES;
    const float* __restrict__ lrow = adj_label + (size_t)i * N_NODES;
    float pos = 0.0f;
#pragma unroll
    for (int it = 0; it < 4; it++) {
        int j = tid + it * 1024;
        float t = trow[j];
        sv[j] = t;
        pos += __expf(2.0f * t) * lrow[j];
    }
    red[tid] = pos;
    __syncthreads();
    for (int s = 512; s > 0; s >>= 1) {
        if (tid < s) red[tid] += red[tid + s];
        __syncthreads();
    }
    const float posSum = red[0];
    __syncthreads();
    for (int kk = 2; kk <= 4096; kk <<= 1) {
        for (int j = kk >> 1; j > 0; j >>= 1) {
#pragma unroll
            for (int it = 0; it < 4; it++) {
                int idx = tid + it * 1024;
                int ixj = idx ^ j;
                if (ixj > idx) {
                    float a = sv[idx], b = sv[ixj];
                    bool up = ((idx & kk) == 0);
                    if ((a > b) == up) { sv[idx] = b; sv[ixj] = a; }
                }
            }
            __syncthreads();
        }
    }
    if (tid == 0) {
        float neg = 0.0f;
#pragma unroll
        for (int s = 0; s < N_S; s++) neg += __expf(2.0f * sv[node_index[s]]);
        atomicAdd(&g_node_loss, (logf(neg) - logf(posSum)) * (1.0f / 4096.0f));
    }
}

// ---------------- finalize ----------------
__global__ void k_finalize(float* __restrict__ out) {
    out[4 * N_NODES + 0] = g_feat_loss;
    out[4 * N_NODES + 1] = g_node_loss;
}

// ---------------- launch ----------------
extern "C" void kernel_launch(void* const* d_in, const int* in_sizes, int n_in,
                              void* d_out, int out_size) {
    const float* seq1      = (const float*)d_in[0];
    const float* seq2      = (const float*)d_in[1];
    const float* adj       = (const float*)d_in[2];
    const float* diff      = (const float*)d_in[3];
    const float* adj_label = (const float*)d_in[4];
    const int*   feat_idx  = (const int*)d_in[5];
    const int*   node_idx  = (const int*)d_in[6];
    const float* W1        = (const float*)d_in[7];
    const float* b1        = (const float*)d_in[8];
    const float* a1        = (const float*)d_in[9];
    const float* W2        = (const float*)d_in[10];
    const float* b2        = (const float*)d_in[11];
    const float* a2        = (const float*)d_in[12];
    const float* Wd        = (const float*)d_in[13];
    const float* bd        = (const float*)d_in[14];
    float* out = (float*)d_out;

    cudaFuncSetAttribute(k_gemm_ftsT, cudaFuncAttributeMaxDynamicSharedMemorySize, SMEM_TOTAL_G);
    cudaFuncSetAttribute(k_gemm_prop, cudaFuncAttributeMaxDynamicSharedMemorySize, SMEM_TOTAL_G);
    cudaFuncSetAttribute(k_gemm_node, cudaFuncAttributeMaxDynamicSharedMemorySize, SMEM_TOTAL_G);

    // device-global addresses for cvt targets
    float *adjc, *diffc, *seqc0, *seqc1, *wc0, *wc1;
    cudaGetSymbolAddress((void**)&adjc,  g_adjc);
    cudaGetSymbolAddress((void**)&diffc, g_diffc);
    cudaGetSymbolAddress((void**)&seqc0, g_seqc);
    seqc1 = seqc0 + N_NODES * N_INF;
    cudaGetSymbolAddress((void**)&wc0, g_Wc);
    wc1 = wc0 + N_HID * N_INF;

    k_init<<<(N_HID * N_HID + 255) / 256, 256>>>();
    {
        const int NB = 256;
        int n4 = N_NODES * N_NODES / 4;
        k_cvt<<<(n4 + NB - 1) / NB, NB>>>((const float4*)adj,  (float4*)adjc,  n4);
        k_cvt<<<(n4 + NB - 1) / NB, NB>>>((const float4*)diff, (float4*)diffc, n4);
        int s4 = N_NODES * N_INF / 4;
        k_cvt<<<(s4 + NB - 1) / NB, NB>>>((const float4*)seq1, (float4*)seqc0, s4);
        k_cvt<<<(s4 + NB - 1) / NB, NB>>>((const float4*)seq2, (float4*)seqc1, s4);
        int w4 = N_HID * N_INF / 4;
        k_cvt<<<(w4 + NB - 1) / NB, NB>>>((const float4*)W1, (float4*)wc0, w4);
        k_cvt<<<(w4 + NB - 1) / NB, NB>>>((const float4*)W2, (float4*)wc1, w4);
    }
    k_gemm_ftsT<<<dim3(16, 4, 4), 256, SMEM_TOTAL_G>>>();
    k_gemm_prop<<<dim3(2, 32, 4), 256, SMEM_TOTAL_G>>>(b1, b2, a1, a2);
    k_compute_Z<<<N_NODES, 512>>>();
    k_col_reduce<<<dim3(16, 3), 256>>>();
    k_compute_u<<<1, 512>>>(Wd);
    k_ret<<<dim3(512, 4), 256>>>(bd, out);
    k_gemm_G<<<dim3(4, 4, 8), 256>>>();
    k_feat_loss<<<512, 512>>>(feat_idx);
    k_gemm_node<<<dim3(16, 32), 256, SMEM_TOTAL_G>>>();
    k_node_row<<<N_NODES, 1024>>>(adj_label, node_idx);
    k_finalize<<<1, 1>>>(out);
}

// round 4
// speedup vs baseline: 2.5477x; 1.1038x over previous
#include <cuda_runtime.h>
#include <math.h>
#include <stdint.h>

#define N_NODES 4096
#define N_HID   512
#define N_INF   512
#define N_S     10

// ---------------- scratch ----------------
__device__ float g_adjc[(size_t)N_NODES * N_NODES];
__device__ float g_diffc[(size_t)N_NODES * N_NODES];
__device__ float g_seqc[2][N_NODES * N_INF];
__device__ float g_Wc[2][N_HID * N_INF];
__device__ float g_fts[4][N_HID * N_NODES];          // ftsT: [h][node], tf32-rounded
__device__ float g_h[4][N_NODES * N_HID];            // h1..h4
__device__ float g_Z[N_NODES * N_HID];               // h1+h2, tf32-rounded
__device__ float g_G[N_HID * N_HID];
__device__ float g_node_sq[(size_t)N_NODES * N_NODES];
__device__ float g_csum[2][N_HID];
__device__ float g_u[2][N_HID];
__device__ float g_rninv[N_NODES];
__device__ float g_cninv[N_HID];
__device__ float g_feat_loss;
__device__ float g_node_loss;

// ---------------- helpers ----------------
__device__ __forceinline__ unsigned f2tf32(float x) {
    unsigned r;
    asm("cvt.rna.tf32.f32 %0, %1;" : "=r"(r) : "f"(x));
    return r;
}

__device__ __forceinline__ void mma8(float (&c)[4], const unsigned (&a)[4],
                                     const unsigned (&b)[2]) {
    asm volatile(
        "mma.sync.aligned.m16n8k8.row.col.f32.tf32.tf32.f32 "
        "{%0,%1,%2,%3}, {%4,%5,%6,%7}, {%8,%9}, {%0,%1,%2,%3};\n"
        : "+f"(c[0]), "+f"(c[1]), "+f"(c[2]), "+f"(c[3])
        : "r"(a[0]), "r"(a[1]), "r"(a[2]), "r"(a[3]), "r"(b[0]), "r"(b[1]));
}

__device__ __forceinline__ void ldsm_x4(unsigned (&r)[4], uint32_t addr) {
    asm volatile("ldmatrix.sync.aligned.m8n8.x4.shared.b16 {%0,%1,%2,%3}, [%4];"
                 : "=r"(r[0]), "=r"(r[1]), "=r"(r[2]), "=r"(r[3]) : "r"(addr));
}

__device__ __forceinline__ void cpa16(uint32_t smem, const void* gmem) {
    asm volatile("cp.async.cg.shared.global [%0], [%1], 16;"
                 :: "r"(smem), "l"(gmem));
}

// =========================================================================
// NT pipelined core: C[128,256] = A[M,K] x B[N,K]^T, operands pre-tf32.
// =========================================================================
#define SMEM_A_STAGE 8192
#define SMEM_B_STAGE 16384
#define SMEM_B_BASE  (3 * SMEM_A_STAGE)
#define SMEM_TOTAL_G (SMEM_B_BASE + 3 * SMEM_B_STAGE)

__device__ __forceinline__ void nt_core(
    const float* __restrict__ A, int lda,
    const float* __restrict__ B, int ldb,
    int m0, int n0, int K, float (&acc)[4][8][4])
{
    extern __shared__ char smem[];
    const uint32_t sbase = (uint32_t)__cvta_generic_to_shared(smem);

    const int t = threadIdx.x;
    const int lane = t & 31, warp = t >> 5;
    const int wr = (warp & 1) * 64, wc = (warp >> 1) * 64;
    const int q = lane >> 3, rowin = lane & 7;
    const int qlo = q & 1, qhi = q >> 1;

    uint32_t aR64[4], aSw[4], bR64[4], bSw[4];
#pragma unroll
    for (int mt = 0; mt < 4; mt++) {
        int r = wr + mt * 16 + qlo * 8 + rowin;
        aR64[mt] = r * 64; aSw[mt] = (r >> 1) & 3;
    }
#pragma unroll
    for (int np = 0; np < 4; np++) {
        int r = wc + (np * 2 + qhi) * 8 + rowin;
        bR64[np] = r * 64; bSw[np] = (r >> 1) & 3;
    }

    const int KT = K >> 4;

    auto issue = [&](int kt, int buf) {
        const uint32_t sa = sbase + buf * SMEM_A_STAGE;
        const uint32_t sb = sbase + SMEM_B_BASE + buf * SMEM_B_STAGE;
#pragma unroll
        for (int i = 0; i < 2; i++) {
            int chunk = t + i * 256;
            int r = chunk >> 2, c4 = chunk & 3;
            uint32_t dst = sa + r * 64 + (((unsigned)(c4 ^ ((r >> 1) & 3))) << 4);
            cpa16(dst, A + (size_t)(m0 + r) * lda + kt * 16 + c4 * 4);
        }
#pragma unroll
        for (int i = 0; i < 4; i++) {
            int chunk = t + i * 256;
            int r = chunk >> 2, c4 = chunk & 3;
            uint32_t dst = sb + r * 64 + (((unsigned)(c4 ^ ((r >> 1) & 3))) << 4);
            cpa16(dst, B + (size_t)(n0 + r) * ldb + kt * 16 + c4 * 4);
        }
        asm volatile("cp.async.commit_group;");
    };

    issue(0, 0);
    issue(1, 1);

    for (int kt = 0; kt < KT; kt++) {
        if (kt + 1 < KT) { asm volatile("cp.async.wait_group 1;"); }
        else             { asm volatile("cp.async.wait_group 0;"); }
        __syncthreads();
        if (kt + 2 < KT) issue(kt + 2, (kt + 2) % 3);

        const int buf = kt % 3;
        const uint32_t sa = sbase + buf * SMEM_A_STAGE;
        const uint32_t sb = sbase + SMEM_B_BASE + buf * SMEM_B_STAGE;
#pragma unroll
        for (int ks = 0; ks < 2; ks++) {
            unsigned af[4][4], bf[8][2];
#pragma unroll
            for (int mt = 0; mt < 4; mt++) {
                uint32_t c4 = ks * 2 + qhi;
                ldsm_x4(af[mt], sa + aR64[mt] + ((c4 ^ aSw[mt]) << 4));
            }
#pragma unroll
            for (int np = 0; np < 4; np++) {
                unsigned r4[4];
                uint32_t c4 = ks * 2 + qlo;
                ldsm_x4(r4, sb + bR64[np] + ((c4 ^ bSw[np]) << 4));
                bf[np * 2 + 0][0] = r4[0]; bf[np * 2 + 0][1] = r4[1];
                bf[np * 2 + 1][0] = r4[2]; bf[np * 2 + 1][1] = r4[3];
            }
#pragma unroll
            for (int mt = 0; mt < 4; mt++)
#pragma unroll
                for (int nt = 0; nt < 8; nt++)
                    mma8(acc[mt][nt], af[mt], bf[nt]);
        }
        __syncthreads();
    }
}

#define ZERO_ACC8(acc)                             \
    _Pragma("unroll")                              \
    for (int mt = 0; mt < 4; mt++)                 \
        _Pragma("unroll")                          \
        for (int nt = 0; nt < 8; nt++)             \
            _Pragma("unroll")                      \
            for (int e = 0; e < 4; e++) acc[mt][nt][e] = 0.0f;

// ---------------- init ----------------
__global__ void k_init() {
    int i = blockIdx.x * blockDim.x + threadIdx.x;
    if (i < N_HID * N_HID) g_G[i] = 0.0f;
    if (i == 0) { g_feat_loss = 0.0f; g_node_loss = 0.0f; }
}

// ---------------- fused tf32 pre-convert ----------------
#define CVT_ADJ  4194304
#define CVT_SEQ  524288
#define CVT_W    65536
#define CVT_TOT  (2 * CVT_ADJ + 2 * CVT_SEQ + 2 * CVT_W)

__global__ void k_cvt_all(const float4* __restrict__ adj, const float4* __restrict__ dif,
                          const float4* __restrict__ s1,  const float4* __restrict__ s2,
                          const float4* __restrict__ w1,  const float4* __restrict__ w2)
{
    long off = (long)blockIdx.x * 256 + threadIdx.x;
    const float4* src; float4* dst;
    if (off < CVT_ADJ)                  { src = adj; dst = (float4*)g_adjc; }
    else if ((off -= CVT_ADJ) < CVT_ADJ){ src = dif; dst = (float4*)g_diffc; }
    else if ((off -= CVT_ADJ) < CVT_SEQ){ src = s1;  dst = (float4*)g_seqc[0]; }
    else if ((off -= CVT_SEQ) < CVT_SEQ){ src = s2;  dst = (float4*)g_seqc[1]; }
    else if ((off -= CVT_SEQ) < CVT_W)  { src = w1;  dst = (float4*)g_Wc[0]; }
    else if ((off -= CVT_W) < CVT_W)    { src = w2;  dst = (float4*)g_Wc[1]; }
    else return;
    float4 v = src[off];
    v.x = __uint_as_float(f2tf32(v.x));
    v.y = __uint_as_float(f2tf32(v.y));
    v.z = __uint_as_float(f2tf32(v.z));
    v.w = __uint_as_float(f2tf32(v.w));
    dst[off] = v;
}

// ---------------- ftsT[z] = W[z] x seq[z]^T : M=512, N=4096, K=512 ----------------
__global__ __launch_bounds__(256) void k_gemm_ftsT() {
    const int z = blockIdx.z;
    const float* A = g_Wc[z & 1];
    const float* B = g_seqc[z >> 1];
    float* __restrict__ C = g_fts[z];
    const int m0 = blockIdx.y * 128, n0 = blockIdx.x * 256;

    float acc[4][8][4];
    ZERO_ACC8(acc);
    nt_core(A, N_INF, B, N_INF, m0, n0, N_INF, acc);

    const int lane = threadIdx.x & 31, warp = threadIdx.x >> 5;
    const int g = lane >> 2, t4 = lane & 3;
    const int wr = (warp & 1) * 64, wc = (warp >> 1) * 64;
#pragma unroll
    for (int mt = 0; mt < 4; mt++)
#pragma unroll
        for (int nt = 0; nt < 8; nt++)
#pragma unroll
            for (int e = 0; e < 4; e++) {
                int row = m0 + wr + mt * 16 + g + (e >> 1) * 8;
                int col = n0 + wc + nt * 8 + 2 * t4 + (e & 1);
                C[(size_t)row * N_NODES + col] = __uint_as_float(f2tf32(acc[mt][nt][e]));
            }
}

// ---------------- h[z] = prelu(adj x ftsT^T + b): M=4096, N=512, K=4096 ------------
__global__ __launch_bounds__(256) void k_gemm_prop(
    const float* __restrict__ b1,  const float* __restrict__ b2,
    const float* __restrict__ a1,  const float* __restrict__ a2)
{
    const int z = blockIdx.z;
    const float* A = (z & 1) ? g_diffc : g_adjc;
    const float* B = g_fts[z];
    const float* bias = (z & 1) ? b2 : b1;
    const float slope = (z & 1) ? a2[0] : a1[0];
    float* __restrict__ C = g_h[z];
    const int m0 = blockIdx.y * 128, n0 = blockIdx.x * 256;

    float acc[4][8][4];
    ZERO_ACC8(acc);
    nt_core(A, N_NODES, B, N_NODES, m0, n0, N_NODES, acc);

    const int lane = threadIdx.x & 31, warp = threadIdx.x >> 5;
    const int g = lane >> 2, t4 = lane & 3;
    const int wr = (warp & 1) * 64, wc = (warp >> 1) * 64;
#pragma unroll
    for (int mt = 0; mt < 4; mt++)
#pragma unroll
        for (int nt = 0; nt < 8; nt++)
#pragma unroll
            for (int e = 0; e < 4; e++) {
                int row = m0 + wr + mt * 16 + g + (e >> 1) * 8;
                int col = n0 + wc + nt * 8 + 2 * t4 + (e & 1);
                float v = acc[mt][nt][e] + bias[col];
                v = (v >= 0.0f) ? v : slope * v;
                C[(size_t)row * N_HID + col] = v;
            }
}

// ---------------- node_sq = (Zn Zn^T)^2: M=N=4096, K=512 ----------------
__global__ __launch_bounds__(256) void k_gemm_node() {
    const int m0 = blockIdx.y * 128, n0 = blockIdx.x * 256;

    float acc[4][8][4];
    ZERO_ACC8(acc);
    nt_core(g_Z, N_HID, g_Z, N_HID, m0, n0, N_HID, acc);

    const int lane = threadIdx.x & 31, warp = threadIdx.x >> 5;
    const int g = lane >> 2, t4 = lane & 3;
    const int wr = (warp & 1) * 64, wc = (warp >> 1) * 64;
#pragma unroll
    for (int mt = 0; mt < 4; mt++) {
        int row = m0 + wr + mt * 16 + g;
        float ri0 = g_rninv[row], ri1 = g_rninv[row + 8];
#pragma unroll
        for (int nt = 0; nt < 8; nt++)
#pragma unroll
            for (int e = 0; e < 4; e++) {
                int r = row + (e >> 1) * 8;
                int col = n0 + wc + nt * 8 + 2 * t4 + (e & 1);
                float x = acc[mt][nt][e] * ((e >> 1) ? ri1 : ri0) * g_rninv[col];
                g_node_sq[(size_t)r * N_NODES + col] = x * x;
            }
    }
}

// ---------------- Z = h1 + h2 (tf32-rounded), row inv-norms ----------------
__global__ void k_compute_Z() {
    const int r = blockIdx.x;
    const int c = threadIdx.x;
    float z = g_h[0][(size_t)r * N_HID + c] + g_h[1][(size_t)r * N_HID + c];
    float zr = __uint_as_float(f2tf32(z));
    g_Z[(size_t)r * N_HID + c] = zr;
    __shared__ float red[512];
    red[c] = zr * zr;
    __syncthreads();
    for (int s = 256; s > 0; s >>= 1) {
        if (c < s) red[c] += red[c + s];
        __syncthreads();
    }
    if (c == 0) g_rninv[r] = 1.0f / fmaxf(sqrtf(red[0]), 1e-12f);
}

// ---------------- column reductions ----------------
__global__ void k_col_reduce() {
    const int mode = blockIdx.y;
    const int tx = threadIdx.x & 31;
    const int ty = threadIdx.x >> 5;
    const int col = blockIdx.x * 32 + tx;
    const float* __restrict__ src = (mode == 0) ? g_h[0] : (mode == 1) ? g_h[1] : g_Z;
    float s = 0.0f;
    for (int r = ty; r < N_NODES; r += 8) {
        float v = src[(size_t)r * N_HID + col];
        s += (mode == 2) ? v * v : v;
    }
    __shared__ float sm[8][32];
    sm[ty][tx] = s;
    __syncthreads();
    if (ty == 0) {
        float tot = 0.0f;
#pragma unroll
        for (int k = 0; k < 8; k++) tot += sm[k][tx];
        if (mode == 2) g_cninv[col] = 1.0f / fmaxf(sqrtf(tot), 1e-12f);
        else g_csum[mode][col] = tot;
    }
}

// ---------------- u = Wd @ sigmoid(colmean) ----------------
__global__ void k_compute_u(const float* __restrict__ Wd) {
    __shared__ float c1s[512], c2s[512];
    const int h = threadIdx.x;
    c1s[h] = 1.0f / (1.0f + expf(-g_csum[0][h] * (1.0f / 4096.0f)));
    c2s[h] = 1.0f / (1.0f + expf(-g_csum[1][h] * (1.0f / 4096.0f)));
    __syncthreads();
    float u1 = 0.0f, u2 = 0.0f;
    const float4* Wrow = reinterpret_cast<const float4*>(Wd + (size_t)h * N_HID);
#pragma unroll 4
    for (int k4 = 0; k4 < 128; k4++) {
        float4 w = Wrow[k4];
        int k = k4 * 4;
        u1 += w.x * c1s[k] + w.y * c1s[k + 1] + w.z * c1s[k + 2] + w.w * c1s[k + 3];
        u2 += w.x * c2s[k] + w.y * c2s[k + 1] + w.z * c2s[k + 2] + w.w * c2s[k + 3];
    }
    g_u[0][h] = u1;
    g_u[1][h] = u2;
}

// ---------------- ret ----------------
__global__ void k_ret(const float* __restrict__ bd, float* __restrict__ out) {
    const int q = blockIdx.y;
    const int n = blockIdx.x * 8 + (threadIdx.x >> 5);
    const int lane = threadIdx.x & 31;
    const float* __restrict__ h = (q == 0) ? g_h[1] : (q == 1) ? g_h[0]
                                : (q == 2) ? g_h[3] : g_h[2];
    const float* __restrict__ u = (q == 0 || q == 2) ? g_u[0] : g_u[1];
    float s = 0.0f;
    for (int k = lane; k < N_HID; k += 32)
        s += h[(size_t)n * N_HID + k] * u[k];
#pragma unroll
    for (int o = 16; o > 0; o >>= 1) s += __shfl_down_sync(0xFFFFFFFFu, s, o);
    if (lane == 0) out[q * N_NODES + n] = s + bd[0];
}

// =========================================================================
// TN core for G = Z^T Z, split-K
// =========================================================================
__device__ __forceinline__ void mma_tn_core(
    const float* __restrict__ A, const float* __restrict__ B, int ld,
    int m0, int n0, int K, float (&acc)[4][4][4])
{
    __shared__ unsigned As[2][16][136];
    __shared__ unsigned Bs[2][16][136];
    const int t = threadIdx.x;
    const int lane = t & 31, warp = t >> 5;
    const int g = lane >> 2, t4 = lane & 3;
    const int wr = (warp & 1) * 64, wc = (warp >> 1) * 32;
    const int kr = t >> 5, nseg = (t & 31) * 4;

    const float* Ab = A + (size_t)kr * ld + m0 + nseg;
    const float* Bb = B + (size_t)kr * ld + n0 + nseg;

#define CVT_ST4(dst, row, seg, v)                        \
    dst[row][(seg) + 0] = f2tf32(v.x);                   \
    dst[row][(seg) + 1] = f2tf32(v.y);                   \
    dst[row][(seg) + 2] = f2tf32(v.z);                   \
    dst[row][(seg) + 3] = f2tf32(v.w);

    {
        float4 a0 = *(const float4*)(Ab);
        float4 a1 = *(const float4*)(Ab + (size_t)8 * ld);
        float4 b0 = *(const float4*)(Bb);
        float4 b1 = *(const float4*)(Bb + (size_t)8 * ld);
        CVT_ST4(As[0], kr, nseg, a0); CVT_ST4(As[0], kr + 8, nseg, a1);
        CVT_ST4(Bs[0], kr, nseg, b0); CVT_ST4(Bs[0], kr + 8, nseg, b1);
    }
    __syncthreads();
    const int KT = K >> 4;
    for (int kt = 0; kt < KT; kt++) {
        const int cur = kt & 1;
        float4 a0, a1, b0, b1;
        const bool pf = (kt + 1 < KT);
        if (pf) {
            const float* Ap = Ab + (size_t)(kt + 1) * 16 * ld;
            const float* Bp = Bb + (size_t)(kt + 1) * 16 * ld;
            a0 = *(const float4*)Ap; a1 = *(const float4*)(Ap + (size_t)8 * ld);
            b0 = *(const float4*)Bp; b1 = *(const float4*)(Bp + (size_t)8 * ld);
        }
#pragma unroll
        for (int ks = 0; ks < 2; ks++) {
            const int k = ks * 8;
            unsigned af[4][4], bf[4][2];
#pragma unroll
            for (int mt = 0; mt < 4; mt++) {
                const int r = wr + mt * 16;
                af[mt][0] = As[cur][k + t4][r + g];
                af[mt][1] = As[cur][k + t4][r + g + 8];
                af[mt][2] = As[cur][k + t4 + 4][r + g];
                af[mt][3] = As[cur][k + t4 + 4][r + g + 8];
            }
#pragma unroll
            for (int nt = 0; nt < 4; nt++) {
                const int c = wc + nt * 8 + g;
                bf[nt][0] = Bs[cur][k + t4][c];
                bf[nt][1] = Bs[cur][k + t4 + 4][c];
            }
#pragma unroll
            for (int mt = 0; mt < 4; mt++)
#pragma unroll
                for (int nt = 0; nt < 4; nt++)
                    mma8(acc[mt][nt], af[mt], bf[nt]);
        }
        if (pf) {
            const int nxt = cur ^ 1;
            CVT_ST4(As[nxt], kr, nseg, a0); CVT_ST4(As[nxt], kr + 8, nseg, a1);
            CVT_ST4(Bs[nxt], kr, nseg, b0); CVT_ST4(Bs[nxt], kr + 8, nseg, b1);
        }
        __syncthreads();
    }
}

__global__ __launch_bounds__(256) void k_gemm_G() {
    const int m0 = blockIdx.y * 128, n0 = blockIdx.x * 128;
    const float* Zk = g_Z + (size_t)blockIdx.z * 512 * N_HID;

    float acc[4][4][4];
#pragma unroll
    for (int mt = 0; mt < 4; mt++)
#pragma unroll
        for (int nt = 0; nt < 4; nt++)
#pragma unroll
            for (int e = 0; e < 4; e++) acc[mt][nt][e] = 0.0f;
    mma_tn_core(Zk, Zk, N_HID, m0, n0, 512, acc);

    const int lane = threadIdx.x & 31, warp = threadIdx.x >> 5;
    const int g = lane >> 2, t4 = lane & 3;
    const int wr = (warp & 1) * 64, wc = (warp >> 1) * 32;
#pragma unroll
    for (int mt = 0; mt < 4; mt++)
#pragma unroll
        for (int nt = 0; nt < 4; nt++)
#pragma unroll
            for (int e = 0; e < 4; e++) {
                int row = m0 + wr + mt * 16 + g + (e >> 1) * 8;
                int col = n0 + wc + nt * 8 + 2 * t4 + (e & 1);
                atomicAdd(&g_G[(size_t)row * N_HID + col], acc[mt][nt][e]);
            }
}

// ---------------- feat loss ----------------
__global__ void k_feat_loss(const int* __restrict__ feat_index) {
    const int h = blockIdx.x;
    const int k = threadIdx.x;
    __shared__ float sv[512];
    float feat = g_G[(size_t)h * N_HID + k] * g_cninv[h] * g_cninv[k];
    sv[k] = feat * feat;
    __syncthreads();
    const float diag = sv[h];
    __syncthreads();
    for (int kk = 2; kk <= 512; kk <<= 1) {
        for (int j = kk >> 1; j > 0; j >>= 1) {
            int i = k;
            int ixj = i ^ j;
            if (ixj > i) {
                float a = sv[i], b = sv[ixj];
                bool up = ((i & kk) == 0);
                if ((a > b) == up) { sv[i] = b; sv[ixj] = a; }
            }
            __syncthreads();
        }
    }
    if (k == 0) {
        float neg = 0.0f;
#pragma unroll
        for (int s = 0; s < N_S; s++) neg += expf(2.0f * sv[feat_index[s]]);
        float pos = expf(2.0f * diag);
        atomicAdd(&g_feat_loss, (logf(neg) - logf(pos)) * (1.0f / 512.0f));
    }
}

// =========================================================================
// node loss: register/shuffle bitonic sort of 4096 values, 512 threads,
// 8 contiguous elements per thread. Only j>=256 substages touch smem.
// =========================================================================
__global__ __launch_bounds__(512) void k_node_sel(const float* __restrict__ adj_label,
                                                  const int* __restrict__ node_index) {
    const int i = blockIdx.x;
    const int t = threadIdx.x;
    __shared__ float sm[4096];
    __shared__ float red[512];
    const float* __restrict__ trow = g_node_sq + (size_t)i * N_NODES;
    const float* __restrict__ lrow = adj_label + (size_t)i * N_NODES;

    float v[8];
    float pos = 0.0f;
    {
        const float4* t4p = reinterpret_cast<const float4*>(trow) + t * 2;
        const float4* l4p = reinterpret_cast<const float4*>(lrow) + t * 2;
        float4 a = t4p[0], b = t4p[1];
        float4 la = l4p[0], lb = l4p[1];
        v[0] = a.x; v[1] = a.y; v[2] = a.z; v[3] = a.w;
        v[4] = b.x; v[5] = b.y; v[6] = b.z; v[7] = b.w;
        pos += __expf(2.0f * a.x) * la.x + __expf(2.0f * a.y) * la.y
             + __expf(2.0f * a.z) * la.z + __expf(2.0f * a.w) * la.w
             + __expf(2.0f * b.x) * lb.x + __expf(2.0f * b.y) * lb.y
             + __expf(2.0f * b.z) * lb.z + __expf(2.0f * b.w) * lb.w;
    }
    red[t] = pos;
    __syncthreads();
    for (int s = 256; s > 0; s >>= 1) {
        if (t < s) red[t] += red[t + s];
        __syncthreads();
    }
    const float posSum = red[0];

    // bitonic ascending over idx = t*8 + e
    for (int kk = 2; kk <= 4096; kk <<= 1) {
        for (int j = kk >> 1; j > 0; j >>= 1) {
            if (j >= 256) {
                const int d = j >> 3;
                const bool lower = (t & d) == 0;
                const bool up = ((t & (kk >> 3)) == 0);
                const bool keepmin = (up == lower);
                __syncthreads();
#pragma unroll
                for (int e = 0; e < 8; e++) sm[t * 8 + e] = v[e];
                __syncthreads();
#pragma unroll
                for (int e = 0; e < 8; e++) {
                    float o = sm[(t ^ d) * 8 + e];
                    v[e] = keepmin ? fminf(v[e], o) : fmaxf(v[e], o);
                }
            } else if (j >= 8) {
                const int d = j >> 3;
                const bool lower = (t & d) == 0;
                const bool up = ((t & (kk >> 3)) == 0);
                const bool keepmin = (up == lower);
#pragma unroll
                for (int e = 0; e < 8; e++) {
                    float o = __shfl_xor_sync(0xFFFFFFFFu, v[e], d);
                    v[e] = keepmin ? fminf(v[e], o) : fmaxf(v[e], o);
                }
            } else {
#pragma unroll
                for (int e = 0; e < 8; e++) {
                    if ((e & j) == 0) {
                        int p = e | j;
                        bool up = ((((t << 3) | e) & kk) == 0);
                        float a = v[e], b = v[p];
                        float lo = fminf(a, b), hi = fmaxf(a, b);
                        v[e] = up ? lo : hi;
                        v[p] = up ? hi : lo;
                    }
                }
            }
        }
    }
    __syncthreads();
#pragma unroll
    for (int e = 0; e < 8; e++) sm[t * 8 + e] = v[e];
    __syncthreads();
    if (t == 0) {
        float neg = 0.0f;
#pragma unroll
        for (int s = 0; s < N_S; s++) neg += __expf(2.0f * sm[node_index[s]]);
        atomicAdd(&g_node_loss, (logf(neg) - logf(posSum)) * (1.0f / 4096.0f));
    }
}

// ---------------- finalize ----------------
__global__ void k_finalize(float* __restrict__ out) {
    out[4 * N_NODES + 0] = g_feat_loss;
    out[4 * N_NODES + 1] = g_node_loss;
}

// ---------------- launch ----------------
extern "C" void kernel_launch(void* const* d_in, const int* in_sizes, int n_in,
                              void* d_out, int out_size) {
    const float* seq1      = (const float*)d_in[0];
    const float* seq2      = (const float*)d_in[1];
    const float* adj       = (const float*)d_in[2];
    const float* diff      = (const float*)d_in[3];
    const float* adj_label = (const float*)d_in[4];
    const int*   feat_idx  = (const int*)d_in[5];
    const int*   node_idx  = (const int*)d_in[6];
    const float* b1        = (const float*)d_in[8];
    const float* a1        = (const float*)d_in[9];
    const float* b2        = (const float*)d_in[11];
    const float* a2        = (const float*)d_in[12];
    const float* Wd        = (const float*)d_in[13];
    const float* bd        = (const float*)d_in[14];
    float* out = (float*)d_out;

    cudaFuncSetAttribute(k_gemm_ftsT, cudaFuncAttributeMaxDynamicSharedMemorySize, SMEM_TOTAL_G);
    cudaFuncSetAttribute(k_gemm_prop, cudaFuncAttributeMaxDynamicSharedMemorySize, SMEM_TOTAL_G);
    cudaFuncSetAttribute(k_gemm_node, cudaFuncAttributeMaxDynamicSharedMemorySize, SMEM_TOTAL_G);

    // launch order arranged so launch #6 = k_gemm_prop (ncu -s 5 -c 1 target)
    k_cvt_all<<<(CVT_TOT + 255) / 256, 256>>>(
        (const float4*)adj, (const float4*)diff,
        (const float4*)seq1, (const float4*)seq2,
        (const float4*)d_in[7], (const float4*)d_in[10]);
    k_init<<<(N_HID * N_HID + 255) / 256, 256>>>();
    k_gemm_ftsT<<<dim3(16, 4, 4), 256, SMEM_TOTAL_G>>>();
    k_init<<<(N_HID * N_HID + 255) / 256, 256>>>();   // pad (idempotent)
    k_init<<<(N_HID * N_HID + 255) / 256, 256>>>();   // pad (idempotent)
    k_gemm_prop<<<dim3(2, 32, 4), 256, SMEM_TOTAL_G>>>(b1, b2, a1, a2);
    k_compute_Z<<<N_NODES, 512>>>();
    k_col_reduce<<<dim3(16, 3), 256>>>();
    k_compute_u<<<1, 512>>>(Wd);
    k_ret<<<dim3(512, 4), 256>>>(bd, out);
    k_gemm_G<<<dim3(4, 4, 8), 256>>>();
    k_feat_loss<<<512, 512>>>(feat_idx);
    k_gemm_node<<<dim3(16, 32), 256, SMEM_TOTAL_G>>>();
    k_node_sel<<<N_NODES, 512>>>(adj_label, node_idx);
    k_finalize<<<1, 1>>>(out);
}

// round 6
// speedup vs baseline: 2.6238x; 1.0299x over previous
#include <cuda_runtime.h>
#include <math.h>
#include <stdint.h>

#define N_NODES 4096
#define N_HID   512
#define N_INF   512
#define N_S     10

// ---------------- scratch ----------------
__device__ float g_adjc[(size_t)N_NODES * N_NODES];
__device__ float g_diffc[(size_t)N_NODES * N_NODES];
__device__ float g_seqc[2][N_NODES * N_INF];
__device__ float g_Wc[2][N_HID * N_INF];
__device__ float g_fts[4][N_HID * N_NODES];          // ftsT: [h][node], tf32-rounded
__device__ float g_h[4][N_NODES * N_HID];
__device__ float g_Z[N_NODES * N_HID];
__device__ float g_G[N_HID * N_HID];
__device__ float g_node_sq[(size_t)N_NODES * N_NODES];
__device__ float g_csum[2][N_HID];
__device__ float g_u[2][N_HID];
__device__ float g_rninv[N_NODES];
__device__ float g_cninv[N_HID];
__device__ float g_feat_loss;
__device__ float g_node_loss;

// ---------------- helpers ----------------
__device__ __forceinline__ unsigned f2tf32(float x) {
    unsigned r;
    asm("cvt.rna.tf32.f32 %0, %1;" : "=r"(r) : "f"(x));
    return r;
}

__device__ __forceinline__ void mma8(float (&c)[4], const unsigned (&a)[4],
                                     const unsigned (&b)[2]) {
    asm volatile(
        "mma.sync.aligned.m16n8k8.row.col.f32.tf32.tf32.f32 "
        "{%0,%1,%2,%3}, {%4,%5,%6,%7}, {%8,%9}, {%0,%1,%2,%3};\n"
        : "+f"(c[0]), "+f"(c[1]), "+f"(c[2]), "+f"(c[3])
        : "r"(a[0]), "r"(a[1]), "r"(a[2]), "r"(a[3]), "r"(b[0]), "r"(b[1]));
}

__device__ __forceinline__ void ldsm_x4(unsigned (&r)[4], uint32_t addr) {
    asm volatile("ldmatrix.sync.aligned.m8n8.x4.shared.b16 {%0,%1,%2,%3}, [%4];"
                 : "=r"(r[0]), "=r"(r[1]), "=r"(r[2]), "=r"(r[3]) : "r"(addr));
}

__device__ __forceinline__ void cpa16(uint32_t smem, const void* gmem) {
    asm volatile("cp.async.cg.shared.global [%0], [%1], 16;" :: "r"(smem), "l"(gmem));
}

// =========================================================================
// NT pipelined core: C[128,256] = A[M,K] x B[N,K]^T, operands pre-tf32.
// 256 threads, warp grid 2(M) x 4(N), warp tile 64x64.
// 5 cp.async stages x (A 128x16 + B 256x16) fl = 120KB dynamic smem.
// Swizzle: 16B chunk (r, c4) at byte r*64 + ((c4 ^ ((r>>1)&3))<<4).
// =========================================================================
#define STG_BYTES 24576
#define STG_BOFF  8192
#define SMEM_TOTAL_G (5 * STG_BYTES)

__device__ __forceinline__ void nt_core(
    const float* __restrict__ A, int lda,
    const float* __restrict__ B, int ldb,
    int m0, int n0, int K, float (&acc)[4][8][4])
{
    extern __shared__ char smem[];
    const uint32_t sbase = (uint32_t)__cvta_generic_to_shared(smem);

    const int t = threadIdx.x;
    const int lane = t & 31, warp = t >> 5;
    const int wr = (warp & 1) * 64, wc = (warp >> 1) * 64;
    const int q = lane >> 3, rowin = lane & 7;
    const int qlo = q & 1, qhi = q >> 1;

    uint32_t aR64[4], aSw[4], bR64[4], bSw[4];
#pragma unroll
    for (int mt = 0; mt < 4; mt++) {
        int r = wr + mt * 16 + qlo * 8 + rowin;
        aR64[mt] = r * 64; aSw[mt] = (r >> 1) & 3;
    }
#pragma unroll
    for (int np = 0; np < 4; np++) {
        int r = wc + (np * 2 + qhi) * 8 + rowin;
        bR64[np] = r * 64; bSw[np] = (r >> 1) & 3;
    }

    const int KT = K >> 4;

    auto issue = [&](int kt, int buf) {
        const uint32_t sa = sbase + buf * STG_BYTES;
        const uint32_t sb = sa + STG_BOFF;
#pragma unroll
        for (int i = 0; i < 2; i++) {
            int chunk = t + i * 256;
            int r = chunk >> 2, c4 = chunk & 3;
            uint32_t dst = sa + r * 64 + (((unsigned)(c4 ^ ((r >> 1) & 3))) << 4);
            cpa16(dst, A + (size_t)(m0 + r) * lda + kt * 16 + c4 * 4);
        }
#pragma unroll
        for (int i = 0; i < 4; i++) {
            int chunk = t + i * 256;
            int r = chunk >> 2, c4 = chunk & 3;
            uint32_t dst = sb + r * 64 + (((unsigned)(c4 ^ ((r >> 1) & 3))) << 4);
            cpa16(dst, B + (size_t)(n0 + r) * ldb + kt * 16 + c4 * 4);
        }
        asm volatile("cp.async.commit_group;");
    };

    // prefill 4 stages
#pragma unroll
    for (int s = 0; s < 4; s++)
        if (s < KT) issue(s, s);

    for (int kt = 0; kt < KT; kt++) {
        if (kt + 4 < KT) issue(kt + 4, (kt + 4) % 5);
        const int rem = KT - 1 - kt;
        if (rem >= 4)      asm volatile("cp.async.wait_group 4;");
        else if (rem == 3) asm volatile("cp.async.wait_group 3;");
        else if (rem == 2) asm volatile("cp.async.wait_group 2;");
        else if (rem == 1) asm volatile("cp.async.wait_group 1;");
        else               asm volatile("cp.async.wait_group 0;");
        __syncthreads();

        const int buf = kt % 5;
        const uint32_t sa = sbase + buf * STG_BYTES;
        const uint32_t sb = sa + STG_BOFF;
#pragma unroll
        for (int ks = 0; ks < 2; ks++) {
            unsigned af[4][4], bf[8][2];
#pragma unroll
            for (int mt = 0; mt < 4; mt++) {
                uint32_t c4 = ks * 2 + qhi;
                ldsm_x4(af[mt], sa + aR64[mt] + ((c4 ^ aSw[mt]) << 4));
            }
#pragma unroll
            for (int np = 0; np < 4; np++) {
                unsigned r4[4];
                uint32_t c4 = ks * 2 + qlo;
                ldsm_x4(r4, sb + bR64[np] + ((c4 ^ bSw[np]) << 4));
                bf[np * 2 + 0][0] = r4[0]; bf[np * 2 + 0][1] = r4[1];
                bf[np * 2 + 1][0] = r4[2]; bf[np * 2 + 1][1] = r4[3];
            }
#pragma unroll
            for (int mt = 0; mt < 4; mt++)
#pragma unroll
                for (int nt = 0; nt < 8; nt++)
                    mma8(acc[mt][nt], af[mt], bf[nt]);
        }
        __syncthreads();
    }
}

#define ZERO_ACC8(acc)                             \
    _Pragma("unroll")                              \
    for (int mt = 0; mt < 4; mt++)                 \
        _Pragma("unroll")                          \
        for (int nt = 0; nt < 8; nt++)             \
            _Pragma("unroll")                      \
            for (int e = 0; e < 4; e++) acc[mt][nt][e] = 0.0f;

// ---------------- init ----------------
__global__ void k_init() {
    int i = blockIdx.x * blockDim.x + threadIdx.x;
    if (i < N_HID * N_HID) g_G[i] = 0.0f;
    if (i == 0) { g_feat_loss = 0.0f; g_node_loss = 0.0f; }
}

// ---------------- fused tf32 pre-convert ----------------
#define CVT_ADJ  4194304
#define CVT_SEQ  524288
#define CVT_W    65536
#define CVT_TOT  (2 * CVT_ADJ + 2 * CVT_SEQ + 2 * CVT_W)

__global__ void k_cvt_all(const float4* __restrict__ adj, const float4* __restrict__ dif,
                          const float4* __restrict__ s1,  const float4* __restrict__ s2,
                          const float4* __restrict__ w1,  const float4* __restrict__ w2)
{
    long off = (long)blockIdx.x * 256 + threadIdx.x;
    const float4* src; float4* dst;
    if (off < CVT_ADJ)                   { src = adj; dst = (float4*)g_adjc; }
    else if ((off -= CVT_ADJ) < CVT_ADJ) { src = dif; dst = (float4*)g_diffc; }
    else if ((off -= CVT_ADJ) < CVT_SEQ) { src = s1;  dst = (float4*)g_seqc[0]; }
    else if ((off -= CVT_SEQ) < CVT_SEQ) { src = s2;  dst = (float4*)g_seqc[1]; }
    else if ((off -= CVT_SEQ) < CVT_W)   { src = w1;  dst = (float4*)g_Wc[0]; }
    else if ((off -= CVT_W) < CVT_W)     { src = w2;  dst = (float4*)g_Wc[1]; }
    else return;
    float4 v = src[off];
    v.x = __uint_as_float(f2tf32(v.x));
    v.y = __uint_as_float(f2tf32(v.y));
    v.z = __uint_as_float(f2tf32(v.z));
    v.w = __uint_as_float(f2tf32(v.w));
    dst[off] = v;
}

// ---------------- ftsT[z] = W[z] x seq[z]^T : M=512, N=4096, K=512 ----------------
__global__ __launch_bounds__(256) void k_gemm_ftsT() {
    const int z = blockIdx.z;
    const float* A = g_Wc[z & 1];
    const float* B = g_seqc[z >> 1];
    float* __restrict__ C = g_fts[z];
    const int m0 = blockIdx.y * 128, n0 = blockIdx.x * 256;

    float acc[4][8][4];
    ZERO_ACC8(acc);
    nt_core(A, N_INF, B, N_INF, m0, n0, N_INF, acc);

    const int lane = threadIdx.x & 31, warp = threadIdx.x >> 5;
    const int g = lane >> 2, t4 = lane & 3;
    const int wr = (warp & 1) * 64, wc = (warp >> 1) * 64;
#pragma unroll
    for (int mt = 0; mt < 4; mt++)
#pragma unroll
        for (int nt = 0; nt < 8; nt++) {
            int row = m0 + wr + mt * 16 + g;
            int col = n0 + wc + nt * 8 + 2 * t4;
            float2 v01, v23;
            v01.x = __uint_as_float(f2tf32(acc[mt][nt][0]));
            v01.y = __uint_as_float(f2tf32(acc[mt][nt][1]));
            v23.x = __uint_as_float(f2tf32(acc[mt][nt][2]));
            v23.y = __uint_as_float(f2tf32(acc[mt][nt][3]));
            *(float2*)(C + (size_t)row * N_NODES + col) = v01;
            *(float2*)(C + (size_t)(row + 8) * N_NODES + col) = v23;
        }
}

// ---------------- h[z] = prelu(adj x ftsT^T + b): M=4096, N=512, K=4096 ------------
__global__ __launch_bounds__(256) void k_gemm_prop(
    const float* __restrict__ b1,  const float* __restrict__ b2,
    const float* __restrict__ a1,  const float* __restrict__ a2)
{
    const int z = blockIdx.z;
    const float* A = (z & 1) ? g_diffc : g_adjc;
    const float* B = g_fts[z];
    const float* bias = (z & 1) ? b2 : b1;
    const float slope = (z & 1) ? a2[0] : a1[0];
    float* __restrict__ C = g_h[z];
    const int m0 = blockIdx.y * 128, n0 = blockIdx.x * 256;

    float acc[4][8][4];
    ZERO_ACC8(acc);
    nt_core(A, N_NODES, B, N_NODES, m0, n0, N_NODES, acc);

    const int lane = threadIdx.x & 31, warp = threadIdx.x >> 5;
    const int g = lane >> 2, t4 = lane & 3;
    const int wr = (warp & 1) * 64, wc = (warp >> 1) * 64;
#pragma unroll
    for (int mt = 0; mt < 4; mt++)
#pragma unroll
        for (int nt = 0; nt < 8; nt++) {
            int row = m0 + wr + mt * 16 + g;
            int col = n0 + wc + nt * 8 + 2 * t4;
            float b0 = bias[col], b1v = bias[col + 1];
            float2 v01, v23;
            v01.x = acc[mt][nt][0] + b0;  v01.y = acc[mt][nt][1] + b1v;
            v23.x = acc[mt][nt][2] + b0;  v23.y = acc[mt][nt][3] + b1v;
            v01.x = (v01.x >= 0.0f) ? v01.x : slope * v01.x;
            v01.y = (v01.y >= 0.0f) ? v01.y : slope * v01.y;
            v23.x = (v23.x >= 0.0f) ? v23.x : slope * v23.x;
            v23.y = (v23.y >= 0.0f) ? v23.y : slope * v23.y;
            *(float2*)(C + (size_t)row * N_HID + col) = v01;
            *(float2*)(C + (size_t)(row + 8) * N_HID + col) = v23;
        }
}

// ---------------- node_sq = (Zn Zn^T)^2: M=N=4096, K=512 ----------------
__global__ __launch_bounds__(256) void k_gemm_node() {
    const int m0 = blockIdx.y * 128, n0 = blockIdx.x * 256;

    float acc[4][8][4];
    ZERO_ACC8(acc);
    nt_core(g_Z, N_HID, g_Z, N_HID, m0, n0, N_HID, acc);

    const int lane = threadIdx.x & 31, warp = threadIdx.x >> 5;
    const int g = lane >> 2, t4 = lane & 3;
    const int wr = (warp & 1) * 64, wc = (warp >> 1) * 64;
#pragma unroll
    for (int mt = 0; mt < 4; mt++) {
        int row = m0 + wr + mt * 16 + g;
        float ri0 = g_rninv[row], ri1 = g_rninv[row + 8];
#pragma unroll
        for (int nt = 0; nt < 8; nt++) {
            int col = n0 + wc + nt * 8 + 2 * t4;
            float c0 = g_rninv[col], c1 = g_rninv[col + 1];
            float x0 = acc[mt][nt][0] * ri0 * c0;
            float x1 = acc[mt][nt][1] * ri0 * c1;
            float x2 = acc[mt][nt][2] * ri1 * c0;
            float x3 = acc[mt][nt][3] * ri1 * c1;
            float2 v01, v23;
            v01.x = x0 * x0; v01.y = x1 * x1;
            v23.x = x2 * x2; v23.y = x3 * x3;
            *(float2*)(g_node_sq + (size_t)row * N_NODES + col) = v01;
            *(float2*)(g_node_sq + (size_t)(row + 8) * N_NODES + col) = v23;
        }
    }
}

// ---------------- Z = h1 + h2 (tf32-rounded), row inv-norms ----------------
__global__ void k_compute_Z() {
    const int r = blockIdx.x;
    const int c = threadIdx.x;
    float z = g_h[0][(size_t)r * N_HID + c] + g_h[1][(size_t)r * N_HID + c];
    float zr = __uint_as_float(f2tf32(z));
    g_Z[(size_t)r * N_HID + c] = zr;
    __shared__ float red[512];
    red[c] = zr * zr;
    __syncthreads();
    for (int s = 256; s > 0; s >>= 1) {
        if (c < s) red[c] += red[c + s];
        __syncthreads();
    }
    if (c == 0) g_rninv[r] = 1.0f / fmaxf(sqrtf(red[0]), 1e-12f);
}

// ---------------- column reductions ----------------
__global__ void k_col_reduce() {
    const int mode = blockIdx.y;
    const int tx = threadIdx.x & 31;
    const int ty = threadIdx.x >> 5;
    const int col = blockIdx.x * 32 + tx;
    const float* __restrict__ src = (mode == 0) ? g_h[0] : (mode == 1) ? g_h[1] : g_Z;
    float s = 0.0f;
    for (int r = ty; r < N_NODES; r += 8) {
        float v = src[(size_t)r * N_HID + col];
        s += (mode == 2) ? v * v : v;
    }
    __shared__ float sm[8][32];
    sm[ty][tx] = s;
    __syncthreads();
    if (ty == 0) {
        float tot = 0.0f;
#pragma unroll
        for (int k = 0; k < 8; k++) tot += sm[k][tx];
        if (mode == 2) g_cninv[col] = 1.0f / fmaxf(sqrtf(tot), 1e-12f);
        else g_csum[mode][col] = tot;
    }
}

// ---------------- u = Wd @ sigmoid(colmean) ----------------
__global__ void k_compute_u(const float* __restrict__ Wd) {
    __shared__ float c1s[512], c2s[512];
    const int h = threadIdx.x;
    c1s[h] = 1.0f / (1.0f + expf(-g_csum[0][h] * (1.0f / 4096.0f)));
    c2s[h] = 1.0f / (1.0f + expf(-g_csum[1][h] * (1.0f / 4096.0f)));
    __syncthreads();
    float u1 = 0.0f, u2 = 0.0f;
    const float4* Wrow = reinterpret_cast<const float4*>(Wd + (size_t)h * N_HID);
#pragma unroll 4
    for (int k4 = 0; k4 < 128; k4++) {
        float4 w = Wrow[k4];
        int k = k4 * 4;
        u1 += w.x * c1s[k] + w.y * c1s[k + 1] + w.z * c1s[k + 2] + w.w * c1s[k + 3];
        u2 += w.x * c2s[k] + w.y * c2s[k + 1] + w.z * c2s[k + 2] + w.w * c2s[k + 3];
    }
    g_u[0][h] = u1;
    g_u[1][h] = u2;
}

// ---------------- ret ----------------
__global__ void k_ret(const float* __restrict__ bd, float* __restrict__ out) {
    const int q = blockIdx.y;
    const int n = blockIdx.x * 8 + (threadIdx.x >> 5);
    const int lane = threadIdx.x & 31;
    const float* __restrict__ h = (q == 0) ? g_h[1] : (q == 1) ? g_h[0]
                                : (q == 2) ? g_h[3] : g_h[2];
    const float* __restrict__ u = (q == 0 || q == 2) ? g_u[0] : g_u[1];
    float s = 0.0f;
    for (int k = lane; k < N_HID; k += 32)
        s += h[(size_t)n * N_HID + k] * u[k];
#pragma unroll
    for (int o = 16; o > 0; o >>= 1) s += __shfl_down_sync(0xFFFFFFFFu, s, o);
    if (lane == 0) out[q * N_NODES + n] = s + bd[0];
}

// ---------------- mma.sync TN core for G = Z^T Z (small) ----------------
#define CVT_ST4(dst, row, seg, v)                        \
    dst[row][(seg) + 0] = f2tf32(v.x);                   \
    dst[row][(seg) + 1] = f2tf32(v.y);                   \
    dst[row][(seg) + 2] = f2tf32(v.z);                   \
    dst[row][(seg) + 3] = f2tf32(v.w);

__global__ __launch_bounds__(256) void k_gemm_G() {
    __shared__ unsigned As[2][16][136];
    __shared__ unsigned Bs[2][16][136];
    const int t = threadIdx.x;
    const int lane = t & 31, warp = t >> 5;
    const int g = lane >> 2, t4 = lane & 3;
    const int wr = (warp & 1) * 64, wc = (warp >> 1) * 32;
    const int kr = t >> 5, nseg = (t & 31) * 4;
    const int m0 = blockIdx.y * 128, n0 = blockIdx.x * 128;
    const float* Zk = g_Z + (size_t)blockIdx.z * 512 * N_HID;

    const float* Ab = Zk + (size_t)kr * N_HID + m0 + nseg;
    const float* Bb = Zk + (size_t)kr * N_HID + n0 + nseg;

    float acc[4][4][4];
#pragma unroll
    for (int mt = 0; mt < 4; mt++)
#pragma unroll
        for (int nt = 0; nt < 4; nt++)
#pragma unroll
            for (int e = 0; e < 4; e++) acc[mt][nt][e] = 0.0f;

    {
        float4 a0 = *(const float4*)(Ab);
        float4 a1 = *(const float4*)(Ab + (size_t)8 * N_HID);
        float4 b0 = *(const float4*)(Bb);
        float4 b1 = *(const float4*)(Bb + (size_t)8 * N_HID);
        CVT_ST4(As[0], kr, nseg, a0); CVT_ST4(As[0], kr + 8, nseg, a1);
        CVT_ST4(Bs[0], kr, nseg, b0); CVT_ST4(Bs[0], kr + 8, nseg, b1);
    }
    __syncthreads();
    for (int kt = 0; kt < 32; kt++) {
        const int cur = kt & 1;
        float4 a0, a1, b0, b1;
        const bool pf = (kt + 1 < 32);
        if (pf) {
            const float* Ap = Ab + (size_t)(kt + 1) * 16 * N_HID;
            const float* Bp = Bb + (size_t)(kt + 1) * 16 * N_HID;
            a0 = *(const float4*)Ap; a1 = *(const float4*)(Ap + (size_t)8 * N_HID);
            b0 = *(const float4*)Bp; b1 = *(const float4*)(Bp + (size_t)8 * N_HID);
        }
#pragma unroll
        for (int ks = 0; ks < 2; ks++) {
            const int k = ks * 8;
            unsigned af[4][4], bf[4][2];
#pragma unroll
            for (int mt = 0; mt < 4; mt++) {
                const int r = wr + mt * 16;
                af[mt][0] = As[cur][k + t4][r + g];
                af[mt][1] = As[cur][k + t4][r + g + 8];
                af[mt][2] = As[cur][k + t4 + 4][r + g];
                af[mt][3] = As[cur][k + t4 + 4][r + g + 8];
            }
#pragma unroll
            for (int nt = 0; nt < 4; nt++) {
                const int c = wc + nt * 8 + g;
                bf[nt][0] = Bs[cur][k + t4][c];
                bf[nt][1] = Bs[cur][k + t4 + 4][c];
            }
#pragma unroll
            for (int mt = 0; mt < 4; mt++)
#pragma unroll
                for (int nt = 0; nt < 4; nt++)
                    mma8(acc[mt][nt], af[mt], bf[nt]);
        }
        if (pf) {
            const int nxt = cur ^ 1;
            CVT_ST4(As[nxt], kr, nseg, a0); CVT_ST4(As[nxt], kr + 8, nseg, a1);
            CVT_ST4(Bs[nxt], kr, nseg, b0); CVT_ST4(Bs[nxt], kr + 8, nseg, b1);
        }
        __syncthreads();
    }
#pragma unroll
    for (int mt = 0; mt < 4; mt++)
#pragma unroll
        for (int nt = 0; nt < 4; nt++)
#pragma unroll
            for (int e = 0; e < 4; e++) {
                int row = m0 + wr + mt * 16 + g + (e >> 1) * 8;
                int col = n0 + wc + nt * 8 + 2 * t4 + (e & 1);
                atomicAdd(&g_G[(size_t)row * N_HID + col], acc[mt][nt][e]);
            }
}

// ---------------- feat loss ----------------
__global__ void k_feat_loss(const int* __restrict__ feat_index) {
    const int h = blockIdx.x;
    const int k = threadIdx.x;
    __shared__ float sv[512];
    float feat = g_G[(size_t)h * N_HID + k] * g_cninv[h] * g_cninv[k];
    sv[k] = feat * feat;
    __syncthreads();
    const float diag = sv[h];
    __syncthreads();
    for (int kk = 2; kk <= 512; kk <<= 1) {
        for (int j = kk >> 1; j > 0; j >>= 1) {
            int i = k;
            int ixj = i ^ j;
            if (ixj > i) {
                float a = sv[i], b = sv[ixj];
                bool up = ((i & kk) == 0);
                if ((a > b) == up) { sv[i] = b; sv[ixj] = a; }
            }
            __syncthreads();
        }
    }
    if (k == 0) {
        float neg = 0.0f;
#pragma unroll
        for (int s = 0; s < N_S; s++) neg += expf(2.0f * sv[feat_index[s]]);
        float pos = expf(2.0f * diag);
        atomicAdd(&g_feat_loss, (logf(neg) - logf(pos)) * (1.0f / 512.0f));
    }
}

// ---------------- node loss: register/shuffle bitonic ----------------
__global__ __launch_bounds__(512) void k_node_sel(const float* __restrict__ adj_label,
                                                  const int* __restrict__ node_index) {
    const int i = blockIdx.x;
    const int t = threadIdx.x;
    __shared__ float sm[4096];
    __shared__ float red[512];
    const float* __restrict__ trow = g_node_sq + (size_t)i * N_NODES;
    const float* __restrict__ lrow = adj_label + (size_t)i * N_NODES;

    float v[8];
    float pos = 0.0f;
    {
        const float4* t4p = reinterpret_cast<const float4*>(trow) + t * 2;
        const float4* l4p = reinterpret_cast<const float4*>(lrow) + t * 2;
        float4 a = t4p[0], b = t4p[1];
        float4 la = l4p[0], lb = l4p[1];
        v[0] = a.x; v[1] = a.y; v[2] = a.z; v[3] = a.w;
        v[4] = b.x; v[5] = b.y; v[6] = b.z; v[7] = b.w;
        pos += __expf(2.0f * a.x) * la.x + __expf(2.0f * a.y) * la.y
             + __expf(2.0f * a.z) * la.z + __expf(2.0f * a.w) * la.w
             + __expf(2.0f * b.x) * lb.x + __expf(2.0f * b.y) * lb.y
             + __expf(2.0f * b.z) * lb.z + __expf(2.0f * b.w) * lb.w;
    }
    red[t] = pos;
    __syncthreads();
    for (int s = 256; s > 0; s >>= 1) {
        if (t < s) red[t] += red[t + s];
        __syncthreads();
    }
    const float posSum = red[0];

    for (int kk = 2; kk <= 4096; kk <<= 1) {
        for (int j = kk >> 1; j > 0; j >>= 1) {
            if (j >= 256) {
                const int d = j >> 3;
                const bool lower = (t & d) == 0;
                const bool up = ((t & (kk >> 3)) == 0);
                const bool keepmin = (up == lower);
                __syncthreads();
#pragma unroll
                for (int e = 0; e < 8; e++) sm[t * 8 + e] = v[e];
                __syncthreads();
#pragma unroll
                for (int e = 0; e < 8; e++) {
                    float o = sm[(t ^ d) * 8 + e];
                    v[e] = keepmin ? fminf(v[e], o) : fmaxf(v[e], o);
                }
            } else if (j >= 8) {
                const int d = j >> 3;
                const bool lower = (t & d) == 0;
                const bool up = ((t & (kk >> 3)) == 0);
                const bool keepmin = (up == lower);
#pragma unroll
                for (int e = 0; e < 8; e++) {
                    float o = __shfl_xor_sync(0xFFFFFFFFu, v[e], d);
                    v[e] = keepmin ? fminf(v[e], o) : fmaxf(v[e], o);
                }
            } else {
#pragma unroll
                for (int e = 0; e < 8; e++) {
                    if ((e & j) == 0) {
                        int p = e | j;
                        bool up = ((((t << 3) | e) & kk) == 0);
                        float a = v[e], b = v[p];
                        float lo = fminf(a, b), hi = fmaxf(a, b);
                        v[e] = up ? lo : hi;
                        v[p] = up ? hi : lo;
                    }
                }
            }
        }
    }
    __syncthreads();
#pragma unroll
    for (int e = 0; e < 8; e++) sm[t * 8 + e] = v[e];
    __syncthreads();
    if (t == 0) {
        float neg = 0.0f;
#pragma unroll
        for (int s = 0; s < N_S; s++) neg += __expf(2.0f * sm[node_index[s]]);
        atomicAdd(&g_node_loss, (logf(neg) - logf(posSum)) * (1.0f / 4096.0f));
    }
}

// ---------------- finalize ----------------
__global__ void k_finalize(float* __restrict__ out) {
    out[4 * N_NODES + 0] = g_feat_loss;
    out[4 * N_NODES + 1] = g_node_loss;
}

// ---------------- launch ----------------
extern "C" void kernel_launch(void* const* d_in, const int* in_sizes, int n_in,
                              void* d_out, int out_size) {
    const float* seq1      = (const float*)d_in[0];
    const float* seq2      = (const float*)d_in[1];
    const float* adj       = (const float*)d_in[2];
    const float* diff      = (const float*)d_in[3];
    const float* adj_label = (const float*)d_in[4];
    const int*   feat_idx  = (const int*)d_in[5];
    const int*   node_idx  = (const int*)d_in[6];
    const float* b1        = (const float*)d_in[8];
    const float* a1        = (const float*)d_in[9];
    const float* b2        = (const float*)d_in[11];
    const float* a2        = (const float*)d_in[12];
    const float* Wd        = (const float*)d_in[13];
    const float* bd        = (const float*)d_in[14];
    float* out = (float*)d_out;

    cudaFuncSetAttribute(k_gemm_ftsT, cudaFuncAttributeMaxDynamicSharedMemorySize, SMEM_TOTAL_G);
    cudaFuncSetAttribute(k_gemm_prop, cudaFuncAttributeMaxDynamicSharedMemorySize, SMEM_TOTAL_G);
    cudaFuncSetAttribute(k_gemm_node, cudaFuncAttributeMaxDynamicSharedMemorySize, SMEM_TOTAL_G);

    // launch #4 = k_gemm_prop (observed ncu capture slot)
    k_cvt_all<<<(CVT_TOT + 255) / 256, 256>>>(
        (const float4*)adj, (const float4*)diff,
        (const float4*)seq1, (const float4*)seq2,
        (const float4*)d_in[7], (const float4*)d_in[10]);
    k_init<<<(N_HID * N_HID + 255) / 256, 256>>>();
    k_gemm_ftsT<<<dim3(16, 4, 4), 256, SMEM_TOTAL_G>>>();
    k_gemm_prop<<<dim3(2, 32, 4), 256, SMEM_TOTAL_G>>>(b1, b2, a1, a2);
    k_compute_Z<<<N_NODES, 512>>>();
    k_col_reduce<<<dim3(16, 3), 256>>>();
    k_compute_u<<<1, 512>>>(Wd);
    k_ret<<<dim3(512, 4), 256>>>(bd, out);
    k_gemm_G<<<dim3(4, 4, 8), 256>>>();
    k_feat_loss<<<512, 512>>>(feat_idx);
    k_gemm_node<<<dim3(16, 32), 256, SMEM_TOTAL_G>>>();
    k_node_sel<<<N_NODES, 512>>>(adj_label, node_idx);
    k_finalize<<<1, 1>>>(out);
}

// round 7
// speedup vs baseline: 2.7655x; 1.0540x over previous
#include <cuda_runtime.h>
#include <math.h>
#include <stdint.h>

#define N_NODES 4096
#define N_HID   512
#define N_INF   512
#define N_S     10

// ---------------- scratch ----------------
__device__ float g_adjc[(size_t)N_NODES * N_NODES];
__device__ float g_diffc[(size_t)N_NODES * N_NODES];
__device__ float g_seqc[2][N_NODES * N_INF];
__device__ float g_Wc[2][N_HID * N_INF];
__device__ float g_fts[4][N_HID * N_NODES];          // ftsT: [h][node], tf32-rounded
__device__ float g_h[4][N_NODES * N_HID];
__device__ float g_Z[N_NODES * N_HID];
__device__ float g_G[N_HID * N_HID];
__device__ float g_node_sq[(size_t)N_NODES * N_NODES];
__device__ float g_csum[2][N_HID];
__device__ float g_u[2][N_HID];
__device__ float g_rninv[N_NODES];
__device__ float g_cninv[N_HID];
__device__ float g_feat_loss;
__device__ float g_node_loss;

// ---------------- helpers ----------------
__device__ __forceinline__ unsigned f2tf32(float x) {
    unsigned r;
    asm("cvt.rna.tf32.f32 %0, %1;" : "=r"(r) : "f"(x));
    return r;
}

__device__ __forceinline__ void mma8(float (&c)[4], const unsigned (&a)[4],
                                     const unsigned (&b)[2]) {
    asm volatile(
        "mma.sync.aligned.m16n8k8.row.col.f32.tf32.tf32.f32 "
        "{%0,%1,%2,%3}, {%4,%5,%6,%7}, {%8,%9}, {%0,%1,%2,%3};\n"
        : "+f"(c[0]), "+f"(c[1]), "+f"(c[2]), "+f"(c[3])
        : "r"(a[0]), "r"(a[1]), "r"(a[2]), "r"(a[3]), "r"(b[0]), "r"(b[1]));
}

__device__ __forceinline__ void ldsm_x4(unsigned (&r)[4], uint32_t addr) {
    asm volatile("ldmatrix.sync.aligned.m8n8.x4.shared.b16 {%0,%1,%2,%3}, [%4];"
                 : "=r"(r[0]), "=r"(r[1]), "=r"(r[2]), "=r"(r[3]) : "r"(addr));
}

__device__ __forceinline__ void cpa16(uint32_t smem, const void* gmem) {
    asm volatile("cp.async.cg.shared.global [%0], [%1], 16;" :: "r"(smem), "l"(gmem));
}

// =========================================================================
// NT pipelined core: C[128,128] = A[M,K] x B[N,K]^T, operands pre-tf32.
// 256 threads, warp grid 2(M) x 4(N), warp tile 64x32. 2 CTAs/SM.
// 5 cp.async stages x (A 128x16 + B 128x16) fl = 80KB dynamic smem.
// Swizzle: 16B chunk (r, c4) at byte r*64 + ((c4 ^ ((r>>1)&3))<<4).
// =========================================================================
#define STG_BYTES 16384
#define STG_BOFF  8192
#define SMEM_TOTAL_G (5 * STG_BYTES)

__device__ __forceinline__ void nt_core(
    const float* __restrict__ A, int lda,
    const float* __restrict__ B, int ldb,
    int m0, int n0, int K, float (&acc)[4][4][4])
{
    extern __shared__ char smem[];
    const uint32_t sbase = (uint32_t)__cvta_generic_to_shared(smem);

    const int t = threadIdx.x;
    const int lane = t & 31, warp = t >> 5;
    const int wr = (warp & 1) * 64, wc = (warp >> 1) * 32;
    const int q = lane >> 3, rowin = lane & 7;
    const int qlo = q & 1, qhi = q >> 1;

    uint32_t aR64[4], aSw[4], bR64[2], bSw[2];
#pragma unroll
    for (int mt = 0; mt < 4; mt++) {
        int r = wr + mt * 16 + qlo * 8 + rowin;
        aR64[mt] = r * 64; aSw[mt] = (r >> 1) & 3;
    }
#pragma unroll
    for (int np = 0; np < 2; np++) {
        int r = wc + (np * 2 + qhi) * 8 + rowin;
        bR64[np] = r * 64; bSw[np] = (r >> 1) & 3;
    }

    const int KT = K >> 4;

    auto issue = [&](int kt, int buf) {
        const uint32_t sa = sbase + buf * STG_BYTES;
        const uint32_t sb = sa + STG_BOFF;
#pragma unroll
        for (int i = 0; i < 2; i++) {
            int chunk = t + i * 256;
            int r = chunk >> 2, c4 = chunk & 3;
            uint32_t sw = (((unsigned)(c4 ^ ((r >> 1) & 3))) << 4);
            cpa16(sa + r * 64 + sw, A + (size_t)(m0 + r) * lda + kt * 16 + c4 * 4);
            cpa16(sb + r * 64 + sw, B + (size_t)(n0 + r) * ldb + kt * 16 + c4 * 4);
        }
        asm volatile("cp.async.commit_group;");
    };

    // prefill 4 stages
#pragma unroll
    for (int s = 0; s < 4; s++)
        if (s < KT) issue(s, s);

    for (int kt = 0; kt < KT; kt++) {
        if (kt + 4 < KT) issue(kt + 4, (kt + 4) % 5);
        const int rem = KT - 1 - kt;
        if (rem >= 4)      asm volatile("cp.async.wait_group 4;");
        else if (rem == 3) asm volatile("cp.async.wait_group 3;");
        else if (rem == 2) asm volatile("cp.async.wait_group 2;");
        else if (rem == 1) asm volatile("cp.async.wait_group 1;");
        else               asm volatile("cp.async.wait_group 0;");
        __syncthreads();

        const int buf = kt % 5;
        const uint32_t sa = sbase + buf * STG_BYTES;
        const uint32_t sb = sa + STG_BOFF;
#pragma unroll
        for (int ks = 0; ks < 2; ks++) {
            unsigned af[4][4], bf[4][2];
#pragma unroll
            for (int mt = 0; mt < 4; mt++) {
                uint32_t c4 = ks * 2 + qhi;
                ldsm_x4(af[mt], sa + aR64[mt] + ((c4 ^ aSw[mt]) << 4));
            }
#pragma unroll
            for (int np = 0; np < 2; np++) {
                unsigned r4[4];
                uint32_t c4 = ks * 2 + qlo;
                ldsm_x4(r4, sb + bR64[np] + ((c4 ^ bSw[np]) << 4));
                bf[np * 2 + 0][0] = r4[0]; bf[np * 2 + 0][1] = r4[1];
                bf[np * 2 + 1][0] = r4[2]; bf[np * 2 + 1][1] = r4[3];
            }
#pragma unroll
            for (int mt = 0; mt < 4; mt++)
#pragma unroll
                for (int nt = 0; nt < 4; nt++)
                    mma8(acc[mt][nt], af[mt], bf[nt]);
        }
        __syncthreads();
    }
}

#define ZERO_ACC4(acc)                             \
    _Pragma("unroll")                              \
    for (int mt = 0; mt < 4; mt++)                 \
        _Pragma("unroll")                          \
        for (int nt = 0; nt < 4; nt++)             \
            _Pragma("unroll")                      \
            for (int e = 0; e < 4; e++) acc[mt][nt][e] = 0.0f;

// ---------------- init ----------------
__global__ void k_init() {
    int i = blockIdx.x * blockDim.x + threadIdx.x;
    if (i < N_HID * N_HID) g_G[i] = 0.0f;
    if (i == 0) { g_feat_loss = 0.0f; g_node_loss = 0.0f; }
}

// ---------------- fused tf32 pre-convert ----------------
#define CVT_ADJ  4194304
#define CVT_SEQ  524288
#define CVT_W    65536
#define CVT_TOT  (2 * CVT_ADJ + 2 * CVT_SEQ + 2 * CVT_W)

__global__ void k_cvt_all(const float4* __restrict__ adj, const float4* __restrict__ dif,
                          const float4* __restrict__ s1,  const float4* __restrict__ s2,
                          const float4* __restrict__ w1,  const float4* __restrict__ w2)
{
    long off = (long)blockIdx.x * 256 + threadIdx.x;
    const float4* src; float4* dst;
    if (off < CVT_ADJ)                   { src = adj; dst = (float4*)g_adjc; }
    else if ((off -= CVT_ADJ) < CVT_ADJ) { src = dif; dst = (float4*)g_diffc; }
    else if ((off -= CVT_ADJ) < CVT_SEQ) { src = s1;  dst = (float4*)g_seqc[0]; }
    else if ((off -= CVT_SEQ) < CVT_SEQ) { src = s2;  dst = (float4*)g_seqc[1]; }
    else if ((off -= CVT_SEQ) < CVT_W)   { src = w1;  dst = (float4*)g_Wc[0]; }
    else if ((off -= CVT_W) < CVT_W)     { src = w2;  dst = (float4*)g_Wc[1]; }
    else return;
    float4 v = src[off];
    v.x = __uint_as_float(f2tf32(v.x));
    v.y = __uint_as_float(f2tf32(v.y));
    v.z = __uint_as_float(f2tf32(v.z));
    v.w = __uint_as_float(f2tf32(v.w));
    dst[off] = v;
}

// ---------------- ftsT[z] = W[z] x seq[z]^T : M=512, N=4096, K=512 ----------------
__global__ __launch_bounds__(256, 2) void k_gemm_ftsT() {
    const int z = blockIdx.z;
    const float* A = g_Wc[z & 1];
    const float* B = g_seqc[z >> 1];
    float* __restrict__ C = g_fts[z];
    const int m0 = blockIdx.y * 128, n0 = blockIdx.x * 128;

    float acc[4][4][4];
    ZERO_ACC4(acc);
    nt_core(A, N_INF, B, N_INF, m0, n0, N_INF, acc);

    const int lane = threadIdx.x & 31, warp = threadIdx.x >> 5;
    const int g = lane >> 2, t4 = lane & 3;
    const int wr = (warp & 1) * 64, wc = (warp >> 1) * 32;
#pragma unroll
    for (int mt = 0; mt < 4; mt++)
#pragma unroll
        for (int nt = 0; nt < 4; nt++) {
            int row = m0 + wr + mt * 16 + g;
            int col = n0 + wc + nt * 8 + 2 * t4;
            float2 v01, v23;
            v01.x = __uint_as_float(f2tf32(acc[mt][nt][0]));
            v01.y = __uint_as_float(f2tf32(acc[mt][nt][1]));
            v23.x = __uint_as_float(f2tf32(acc[mt][nt][2]));
            v23.y = __uint_as_float(f2tf32(acc[mt][nt][3]));
            *(float2*)(C + (size_t)row * N_NODES + col) = v01;
            *(float2*)(C + (size_t)(row + 8) * N_NODES + col) = v23;
        }
}

// ---------------- h[z] = prelu(adj x ftsT^T + b): M=4096, N=512, K=4096 ------------
__global__ __launch_bounds__(256, 2) void k_gemm_prop(
    const float* __restrict__ b1,  const float* __restrict__ b2,
    const float* __restrict__ a1,  const float* __restrict__ a2)
{
    const int z = blockIdx.z;
    const float* A = (z & 1) ? g_diffc : g_adjc;
    const float* B = g_fts[z];
    const float* bias = (z & 1) ? b2 : b1;
    const float slope = (z & 1) ? a2[0] : a1[0];
    float* __restrict__ C = g_h[z];
    const int m0 = blockIdx.y * 128, n0 = blockIdx.x * 128;

    float acc[4][4][4];
    ZERO_ACC4(acc);
    nt_core(A, N_NODES, B, N_NODES, m0, n0, N_NODES, acc);

    const int lane = threadIdx.x & 31, warp = threadIdx.x >> 5;
    const int g = lane >> 2, t4 = lane & 3;
    const int wr = (warp & 1) * 64, wc = (warp >> 1) * 32;
#pragma unroll
    for (int mt = 0; mt < 4; mt++)
#pragma unroll
        for (int nt = 0; nt < 4; nt++) {
            int row = m0 + wr + mt * 16 + g;
            int col = n0 + wc + nt * 8 + 2 * t4;
            float b0 = bias[col], b1v = bias[col + 1];
            float2 v01, v23;
            v01.x = acc[mt][nt][0] + b0;  v01.y = acc[mt][nt][1] + b1v;
            v23.x = acc[mt][nt][2] + b0;  v23.y = acc[mt][nt][3] + b1v;
            v01.x = (v01.x >= 0.0f) ? v01.x : slope * v01.x;
            v01.y = (v01.y >= 0.0f) ? v01.y : slope * v01.y;
            v23.x = (v23.x >= 0.0f) ? v23.x : slope * v23.x;
            v23.y = (v23.y >= 0.0f) ? v23.y : slope * v23.y;
            *(float2*)(C + (size_t)row * N_HID + col) = v01;
            *(float2*)(C + (size_t)(row + 8) * N_HID + col) = v23;
        }
}

// ---------------- node_sq = (Zn Zn^T)^2: M=N=4096, K=512 ----------------
__global__ __launch_bounds__(256, 2) void k_gemm_node() {
    const int m0 = blockIdx.y * 128, n0 = blockIdx.x * 128;

    float acc[4][4][4];
    ZERO_ACC4(acc);
    nt_core(g_Z, N_HID, g_Z, N_HID, m0, n0, N_HID, acc);

    const int lane = threadIdx.x & 31, warp = threadIdx.x >> 5;
    const int g = lane >> 2, t4 = lane & 3;
    const int wr = (warp & 1) * 64, wc = (warp >> 1) * 32;
#pragma unroll
    for (int mt = 0; mt < 4; mt++) {
        int row = m0 + wr + mt * 16 + g;
        float ri0 = g_rninv[row], ri1 = g_rninv[row + 8];
#pragma unroll
        for (int nt = 0; nt < 4; nt++) {
            int col = n0 + wc + nt * 8 + 2 * t4;
            float c0 = g_rninv[col], c1 = g_rninv[col + 1];
            float x0 = acc[mt][nt][0] * ri0 * c0;
            float x1 = acc[mt][nt][1] * ri0 * c1;
            float x2 = acc[mt][nt][2] * ri1 * c0;
            float x3 = acc[mt][nt][3] * ri1 * c1;
            float2 v01, v23;
            v01.x = x0 * x0; v01.y = x1 * x1;
            v23.x = x2 * x2; v23.y = x3 * x3;
            *(float2*)(g_node_sq + (size_t)row * N_NODES + col) = v01;
            *(float2*)(g_node_sq + (size_t)(row + 8) * N_NODES + col) = v23;
        }
    }
}

// ---------------- Z = h1 + h2 (tf32-rounded), row inv-norms ----------------
__global__ void k_compute_Z() {
    const int r = blockIdx.x;
    const int c = threadIdx.x;
    float z = g_h[0][(size_t)r * N_HID + c] + g_h[1][(size_t)r * N_HID + c];
    float zr = __uint_as_float(f2tf32(z));
    g_Z[(size_t)r * N_HID + c] = zr;
    __shared__ float red[512];
    red[c] = zr * zr;
    __syncthreads();
    for (int s = 256; s > 0; s >>= 1) {
        if (c < s) red[c] += red[c + s];
        __syncthreads();
    }
    if (c == 0) g_rninv[r] = 1.0f / fmaxf(sqrtf(red[0]), 1e-12f);
}

// ---------------- column reductions ----------------
__global__ void k_col_reduce() {
    const int mode = blockIdx.y;
    const int tx = threadIdx.x & 31;
    const int ty = threadIdx.x >> 5;
    const int col = blockIdx.x * 32 + tx;
    const float* __restrict__ src = (mode == 0) ? g_h[0] : (mode == 1) ? g_h[1] : g_Z;
    float s = 0.0f;
    for (int r = ty; r < N_NODES; r += 8) {
        float v = src[(size_t)r * N_HID + col];
        s += (mode == 2) ? v * v : v;
    }
    __shared__ float sm[8][32];
    sm[ty][tx] = s;
    __syncthreads();
    if (ty == 0) {
        float tot = 0.0f;
#pragma unroll
        for (int k = 0; k < 8; k++) tot += sm[k][tx];
        if (mode == 2) g_cninv[col] = 1.0f / fmaxf(sqrtf(tot), 1e-12f);
        else g_csum[mode][col] = tot;
    }
}

// ---------------- u = Wd @ sigmoid(colmean) ----------------
__global__ void k_compute_u(const float* __restrict__ Wd) {
    __shared__ float c1s[512], c2s[512];
    const int h = threadIdx.x;
    c1s[h] = 1.0f / (1.0f + expf(-g_csum[0][h] * (1.0f / 4096.0f)));
    c2s[h] = 1.0f / (1.0f + expf(-g_csum[1][h] * (1.0f / 4096.0f)));
    __syncthreads();
    float u1 = 0.0f, u2 = 0.0f;
    const float4* Wrow = reinterpret_cast<const float4*>(Wd + (size_t)h * N_HID);
#pragma unroll 4
    for (int k4 = 0; k4 < 128; k4++) {
        float4 w = Wrow[k4];
        int k = k4 * 4;
        u1 += w.x * c1s[k] + w.y * c1s[k + 1] + w.z * c1s[k + 2] + w.w * c1s[k + 3];
        u2 += w.x * c2s[k] + w.y * c2s[k + 1] + w.z * c2s[k + 2] + w.w * c2s[k + 3];
    }
    g_u[0][h] = u1;
    g_u[1][h] = u2;
}

// ---------------- ret ----------------
__global__ void k_ret(const float* __restrict__ bd, float* __restrict__ out) {
    const int q = blockIdx.y;
    const int n = blockIdx.x * 8 + (threadIdx.x >> 5);
    const int lane = threadIdx.x & 31;
    const float* __restrict__ h = (q == 0) ? g_h[1] : (q == 1) ? g_h[0]
                                : (q == 2) ? g_h[3] : g_h[2];
    const float* __restrict__ u = (q == 0 || q == 2) ? g_u[0] : g_u[1];
    float s = 0.0f;
    for (int k = lane; k < N_HID; k += 32)
        s += h[(size_t)n * N_HID + k] * u[k];
#pragma unroll
    for (int o = 16; o > 0; o >>= 1) s += __shfl_down_sync(0xFFFFFFFFu, s, o);
    if (lane == 0) out[q * N_NODES + n] = s + bd[0];
}

// ---------------- mma.sync TN core for G = Z^T Z (small) ----------------
#define CVT_ST4(dst, row, seg, v)                        \
    dst[row][(seg) + 0] = f2tf32(v.x);                   \
    dst[row][(seg) + 1] = f2tf32(v.y);                   \
    dst[row][(seg) + 2] = f2tf32(v.z);                   \
    dst[row][(seg) + 3] = f2tf32(v.w);

__global__ __launch_bounds__(256) void k_gemm_G() {
    __shared__ unsigned As[2][16][136];
    __shared__ unsigned Bs[2][16][136];
    const int t = threadIdx.x;
    const int lane = t & 31, warp = t >> 5;
    const int g = lane >> 2, t4 = lane & 3;
    const int wr = (warp & 1) * 64, wc = (warp >> 1) * 32;
    const int kr = t >> 5, nseg = (t & 31) * 4;
    const int m0 = blockIdx.y * 128, n0 = blockIdx.x * 128;
    const float* Zk = g_Z + (size_t)blockIdx.z * 512 * N_HID;

    const float* Ab = Zk + (size_t)kr * N_HID + m0 + nseg;
    const float* Bb = Zk + (size_t)kr * N_HID + n0 + nseg;

    float acc[4][4][4];
#pragma unroll
    for (int mt = 0; mt < 4; mt++)
#pragma unroll
        for (int nt = 0; nt < 4; nt++)
#pragma unroll
            for (int e = 0; e < 4; e++) acc[mt][nt][e] = 0.0f;

    {
        float4 a0 = *(const float4*)(Ab);
        float4 a1 = *(const float4*)(Ab + (size_t)8 * N_HID);
        float4 b0 = *(const float4*)(Bb);
        float4 b1 = *(const float4*)(Bb + (size_t)8 * N_HID);
        CVT_ST4(As[0], kr, nseg, a0); CVT_ST4(As[0], kr + 8, nseg, a1);
        CVT_ST4(Bs[0], kr, nseg, b0); CVT_ST4(Bs[0], kr + 8, nseg, b1);
    }
    __syncthreads();
    for (int kt = 0; kt < 32; kt++) {
        const int cur = kt & 1;
        float4 a0, a1, b0, b1;
        const bool pf = (kt + 1 < 32);
        if (pf) {
            const float* Ap = Ab + (size_t)(kt + 1) * 16 * N_HID;
            const float* Bp = Bb + (size_t)(kt + 1) * 16 * N_HID;
            a0 = *(const float4*)Ap; a1 = *(const float4*)(Ap + (size_t)8 * N_HID);
            b0 = *(const float4*)Bp; b1 = *(const float4*)(Bp + (size_t)8 * N_HID);
        }
#pragma unroll
        for (int ks = 0; ks < 2; ks++) {
            const int k = ks * 8;
            unsigned af[4][4], bf[4][2];
#pragma unroll
            for (int mt = 0; mt < 4; mt++) {
                const int r = wr + mt * 16;
                af[mt][0] = As[cur][k + t4][r + g];
                af[mt][1] = As[cur][k + t4][r + g + 8];
                af[mt][2] = As[cur][k + t4 + 4][r + g];
                af[mt][3] = As[cur][k + t4 + 4][r + g + 8];
            }
#pragma unroll
            for (int nt = 0; nt < 4; nt++) {
                const int c = wc + nt * 8 + g;
                bf[nt][0] = Bs[cur][k + t4][c];
                bf[nt][1] = Bs[cur][k + t4 + 4][c];
            }
#pragma unroll
            for (int mt = 0; mt < 4; mt++)
#pragma unroll
                for (int nt = 0; nt < 4; nt++)
                    mma8(acc[mt][nt], af[mt], bf[nt]);
        }
        if (pf) {
            const int nxt = cur ^ 1;
            CVT_ST4(As[nxt], kr, nseg, a0); CVT_ST4(As[nxt], kr + 8, nseg, a1);
            CVT_ST4(Bs[nxt], kr, nseg, b0); CVT_ST4(Bs[nxt], kr + 8, nseg, b1);
        }
        __syncthreads();
    }
#pragma unroll
    for (int mt = 0; mt < 4; mt++)
#pragma unroll
        for (int nt = 0; nt < 4; nt++)
#pragma unroll
            for (int e = 0; e < 4; e++) {
                int row = m0 + wr + mt * 16 + g + (e >> 1) * 8;
                int col = n0 + wc + nt * 8 + 2 * t4 + (e & 1);
                atomicAdd(&g_G[(size_t)row * N_HID + col], acc[mt][nt][e]);
            }
}

// ---------------- feat loss ----------------
__global__ void k_feat_loss(const int* __restrict__ feat_index) {
    const int h = blockIdx.x;
    const int k = threadIdx.x;
    __shared__ float sv[512];
    float feat = g_G[(size_t)h * N_HID + k] * g_cninv[h] * g_cninv[k];
    sv[k] = feat * feat;
    __syncthreads();
    const float diag = sv[h];
    __syncthreads();
    for (int kk = 2; kk <= 512; kk <<= 1) {
        for (int j = kk >> 1; j > 0; j >>= 1) {
            int i = k;
            int ixj = i ^ j;
            if (ixj > i) {
                float a = sv[i], b = sv[ixj];
                bool up = ((i & kk) == 0);
                if ((a > b) == up) { sv[i] = b; sv[ixj] = a; }
            }
            __syncthreads();
        }
    }
    if (k == 0) {
        float neg = 0.0f;
#pragma unroll
        for (int s = 0; s < N_S; s++) neg += expf(2.0f * sv[feat_index[s]]);
        float pos = expf(2.0f * diag);
        atomicAdd(&g_feat_loss, (logf(neg) - logf(pos)) * (1.0f / 512.0f));
    }
}

// ---------------- node loss: register/shuffle bitonic ----------------
__global__ __launch_bounds__(512) void k_node_sel(const float* __restrict__ adj_label,
                                                  const int* __restrict__ node_index) {
    const int i = blockIdx.x;
    const int t = threadIdx.x;
    __shared__ float sm[4096];
    __shared__ float red[512];
    const float* __restrict__ trow = g_node_sq + (size_t)i * N_NODES;
    const float* __restrict__ lrow = adj_label + (size_t)i * N_NODES;

    float v[8];
    float pos = 0.0f;
    {
        const float4* t4p = reinterpret_cast<const float4*>(trow) + t * 2;
        const float4* l4p = reinterpret_cast<const float4*>(lrow) + t * 2;
        float4 a = t4p[0], b = t4p[1];
        float4 la = l4p[0], lb = l4p[1];
        v[0] = a.x; v[1] = a.y; v[2] = a.z; v[3] = a.w;
        v[4] = b.x; v[5] = b.y; v[6] = b.z; v[7] = b.w;
        pos += __expf(2.0f * a.x) * la.x + __expf(2.0f * a.y) * la.y
             + __expf(2.0f * a.z) * la.z + __expf(2.0f * a.w) * la.w
             + __expf(2.0f * b.x) * lb.x + __expf(2.0f * b.y) * lb.y
             + __expf(2.0f * b.z) * lb.z + __expf(2.0f * b.w) * lb.w;
    }
    red[t] = pos;
    __syncthreads();
    for (int s = 256; s > 0; s >>= 1) {
        if (t < s) red[t] += red[t + s];
        __syncthreads();
    }
    const float posSum = red[0];

    for (int kk = 2; kk <= 4096; kk <<= 1) {
        for (int j = kk >> 1; j > 0; j >>= 1) {
            if (j >= 256) {
                const int d = j >> 3;
                const bool lower = (t & d) == 0;
                const bool up = ((t & (kk >> 3)) == 0);
                const bool keepmin = (up == lower);
                __syncthreads();
#pragma unroll
                for (int e = 0; e < 8; e++) sm[t * 8 + e] = v[e];
                __syncthreads();
#pragma unroll
                for (int e = 0; e < 8; e++) {
                    float o = sm[(t ^ d) * 8 + e];
                    v[e] = keepmin ? fminf(v[e], o) : fmaxf(v[e], o);
                }
            } else if (j >= 8) {
                const int d = j >> 3;
                const bool lower = (t & d) == 0;
                const bool up = ((t & (kk >> 3)) == 0);
                const bool keepmin = (up == lower);
#pragma unroll
                for (int e = 0; e < 8; e++) {
                    float o = __shfl_xor_sync(0xFFFFFFFFu, v[e], d);
                    v[e] = keepmin ? fminf(v[e], o) : fmaxf(v[e], o);
                }
            } else {
#pragma unroll
                for (int e = 0; e < 8; e++) {
                    if ((e & j) == 0) {
                        int p = e | j;
                        bool up = ((((t << 3) | e) & kk) == 0);
                        float a = v[e], b = v[p];
                        float lo = fminf(a, b), hi = fmaxf(a, b);
                        v[e] = up ? lo : hi;
                        v[p] = up ? hi : lo;
                    }
                }
            }
        }
    }
    __syncthreads();
#pragma unroll
    for (int e = 0; e < 8; e++) sm[t * 8 + e] = v[e];
    __syncthreads();
    if (t == 0) {
        float neg = 0.0f;
#pragma unroll
        for (int s = 0; s < N_S; s++) neg += __expf(2.0f * sm[node_index[s]]);
        atomicAdd(&g_node_loss, (logf(neg) - logf(posSum)) * (1.0f / 4096.0f));
    }
}

// ---------------- finalize ----------------
__global__ void k_finalize(float* __restrict__ out) {
    out[4 * N_NODES + 0] = g_feat_loss;
    out[4 * N_NODES + 1] = g_node_loss;
}

// ---------------- launch ----------------
extern "C" void kernel_launch(void* const* d_in, const int* in_sizes, int n_in,
                              void* d_out, int out_size) {
    const float* seq1      = (const float*)d_in[0];
    const float* seq2      = (const float*)d_in[1];
    const float* adj       = (const float*)d_in[2];
    const float* diff      = (const float*)d_in[3];
    const float* adj_label = (const float*)d_in[4];
    const int*   feat_idx  = (const int*)d_in[5];
    const int*   node_idx  = (const int*)d_in[6];
    const float* b1        = (const float*)d_in[8];
    const float* a1        = (const float*)d_in[9];
    const float* b2        = (const float*)d_in[11];
    const float* a2        = (const float*)d_in[12];
    const float* Wd        = (const float*)d_in[13];
    const float* bd        = (const float*)d_in[14];
    float* out = (float*)d_out;

    cudaFuncSetAttribute(k_gemm_ftsT, cudaFuncAttributeMaxDynamicSharedMemorySize, SMEM_TOTAL_G);
    cudaFuncSetAttribute(k_gemm_prop, cudaFuncAttributeMaxDynamicSharedMemorySize, SMEM_TOTAL_G);
    cudaFuncSetAttribute(k_gemm_node, cudaFuncAttributeMaxDynamicSharedMemorySize, SMEM_TOTAL_G);

    // launch #4 = k_gemm_prop (observed ncu capture slot)
    k_cvt_all<<<(CVT_TOT + 255) / 256, 256>>>(
        (const float4*)adj, (const float4*)diff,
        (const float4*)seq1, (const float4*)seq2,
        (const float4*)d_in[7], (const float4*)d_in[10]);
    k_init<<<(N_HID * N_HID + 255) / 256, 256>>>();
    k_gemm_ftsT<<<dim3(32, 4, 4), 256, SMEM_TOTAL_G>>>();
    k_gemm_prop<<<dim3(4, 32, 4), 256, SMEM_TOTAL_G>>>(b1, b2, a1, a2);
    k_compute_Z<<<N_NODES, 512>>>();
    k_col_reduce<<<dim3(16, 3), 256>>>();
    k_compute_u<<<1, 512>>>(Wd);
    k_ret<<<dim3(512, 4), 256>>>(bd, out);
    k_gemm_G<<<dim3(4, 4, 8), 256>>>();
    k_feat_loss<<<512, 512>>>(feat_idx);
    k_gemm_node<<<dim3(32, 32), 256, SMEM_TOTAL_G>>>();
    k_node_sel<<<N_NODES, 512>>>(adj_label, node_idx);
    k_finalize<<<1, 1>>>(out);
}

// round 8
// speedup vs baseline: 2.9936x; 1.0825x over previous
#include <cuda_runtime.h>
#include <math.h>
#include <stdint.h>

#define N_NODES 4096
#define N_HID   512
#define N_INF   512
#define N_S     10

// ---------------- scratch ----------------
__device__ float g_adjc[(size_t)N_NODES * N_NODES];
__device__ float g_diffc[(size_t)N_NODES * N_NODES];
__device__ float g_seqc[2][N_NODES * N_INF];
__device__ float g_Wc[2][N_HID * N_INF];
__device__ float g_fts[4][N_HID * N_NODES];          // ftsT: [h][node], tf32-rounded
__device__ float g_h[4][N_NODES * N_HID];
__device__ float g_Z[N_NODES * N_HID];
__device__ float g_G[N_HID * N_HID];
__device__ float g_node_sq[(size_t)N_NODES * N_NODES];
__device__ float g_csum[2][N_HID];
__device__ float g_u[2][N_HID];
__device__ float g_rninv[N_NODES];
__device__ float g_cninv[N_HID];
__device__ float g_feat_loss;
__device__ float g_node_loss;

// ---------------- helpers ----------------
__device__ __forceinline__ unsigned f2tf32(float x) {
    unsigned r;
    asm("cvt.rna.tf32.f32 %0, %1;" : "=r"(r) : "f"(x));
    return r;
}

__device__ __forceinline__ void mma8(float (&c)[4], const unsigned (&a)[4],
                                     const unsigned (&b)[2]) {
    asm volatile(
        "mma.sync.aligned.m16n8k8.row.col.f32.tf32.tf32.f32 "
        "{%0,%1,%2,%3}, {%4,%5,%6,%7}, {%8,%9}, {%0,%1,%2,%3};\n"
        : "+f"(c[0]), "+f"(c[1]), "+f"(c[2]), "+f"(c[3])
        : "r"(a[0]), "r"(a[1]), "r"(a[2]), "r"(a[3]), "r"(b[0]), "r"(b[1]));
}

__device__ __forceinline__ void ldsm_x4(unsigned (&r)[4], uint32_t addr) {
    asm volatile("ldmatrix.sync.aligned.m8n8.x4.shared.b16 {%0,%1,%2,%3}, [%4];"
                 : "=r"(r[0]), "=r"(r[1]), "=r"(r[2]), "=r"(r[3]) : "r"(addr));
}

__device__ __forceinline__ void cpa16(uint32_t smem, const void* gmem) {
    asm volatile("cp.async.cg.shared.global [%0], [%1], 16;" :: "r"(smem), "l"(gmem));
}

// =========================================================================
// NT pipelined core: C[128,128] = A[M,K] x B[N,K]^T, operands pre-tf32.
// 256 threads, warp grid 2(M) x 4(N), warp tile 64x32. 2 CTAs/SM.
// BK=32, 3 stages x (A 128x32 + B 128x32) fl = 96KB dynamic smem.
// ONE __syncthreads + ONE wait_group per 32-K iteration.
// Swizzle: 16B chunk (r, c16) at byte r*128 + ((c16 ^ (r&7))<<4)  [SW128].
// =========================================================================
#define STG_BYTES 32768
#define STG_BOFF  16384
#define SMEM_TOTAL_G (3 * STG_BYTES)

__device__ __forceinline__ void nt_core(
    const float* __restrict__ A, int lda,
    const float* __restrict__ B, int ldb,
    int m0, int n0, int K, float (&acc)[4][4][4])
{
    extern __shared__ char smem[];
    const uint32_t sbase = (uint32_t)__cvta_generic_to_shared(smem);

    const int t = threadIdx.x;
    const int lane = t & 31, warp = t >> 5;
    const int wr = (warp & 1) * 64, wc = (warp >> 1) * 32;
    const int q = lane >> 3, rowin = lane & 7;
    const int qlo = q & 1, qhi = q >> 1;

    uint32_t aR[4], aSw[4], bR[2], bSw[2];
#pragma unroll
    for (int mt = 0; mt < 4; mt++) {
        int r = wr + mt * 16 + qlo * 8 + rowin;
        aR[mt] = r * 128; aSw[mt] = r & 7;
    }
#pragma unroll
    for (int np = 0; np < 2; np++) {
        int r = wc + (np * 2 + qhi) * 8 + rowin;
        bR[np] = r * 128; bSw[np] = r & 7;
    }

    const int KT = K >> 5;

    auto issue = [&](int kt, int buf) {
        const uint32_t sa = sbase + buf * STG_BYTES;
        const uint32_t sb = sa + STG_BOFF;
#pragma unroll
        for (int j = 0; j < 4; j++) {
            int c = t + j * 256;
            int r = c >> 3, c16 = c & 7;
            uint32_t sw = ((unsigned)(c16 ^ (r & 7))) << 4;
            cpa16(sa + r * 128 + sw, A + (size_t)(m0 + r) * lda + kt * 32 + c16 * 4);
            cpa16(sb + r * 128 + sw, B + (size_t)(n0 + r) * ldb + kt * 32 + c16 * 4);
        }
        asm volatile("cp.async.commit_group;");
    };

    issue(0, 0);
    issue(1, 1);

    for (int kt = 0; kt < KT; kt++) {
        if (kt + 1 < KT) { asm volatile("cp.async.wait_group 1;"); }
        else             { asm volatile("cp.async.wait_group 0;"); }
        __syncthreads();

        const uint32_t sa = sbase + (kt % 3) * STG_BYTES;
        const uint32_t sb = sa + STG_BOFF;
#pragma unroll
        for (int ks = 0; ks < 4; ks++) {
            unsigned af[4][4], bf[4][2];
#pragma unroll
            for (int mt = 0; mt < 4; mt++) {
                uint32_t c = ks * 2 + qhi;
                ldsm_x4(af[mt], sa + aR[mt] + ((c ^ aSw[mt]) << 4));
            }
#pragma unroll
            for (int np = 0; np < 2; np++) {
                unsigned r4[4];
                uint32_t c = ks * 2 + qlo;
                ldsm_x4(r4, sb + bR[np] + ((c ^ bSw[np]) << 4));
                bf[np * 2 + 0][0] = r4[0]; bf[np * 2 + 0][1] = r4[1];
                bf[np * 2 + 1][0] = r4[2]; bf[np * 2 + 1][1] = r4[3];
            }
#pragma unroll
            for (int mt = 0; mt < 4; mt++)
#pragma unroll
                for (int nt = 0; nt < 4; nt++)
                    mma8(acc[mt][nt], af[mt], bf[nt]);
        }
        if (kt + 2 < KT) issue(kt + 2, (kt + 2) % 3);
    }
}

#define ZERO_ACC4(acc)                             \
    _Pragma("unroll")                              \
    for (int mt = 0; mt < 4; mt++)                 \
        _Pragma("unroll")                          \
        for (int nt = 0; nt < 4; nt++)             \
            _Pragma("unroll")                      \
            for (int e = 0; e < 4; e++) acc[mt][nt][e] = 0.0f;

// ---------------- init ----------------
__global__ void k_init() {
    int i = blockIdx.x * blockDim.x + threadIdx.x;
    if (i < N_HID * N_HID) g_G[i] = 0.0f;
    if (i == 0) { g_feat_loss = 0.0f; g_node_loss = 0.0f; }
}

// ---------------- fused tf32 pre-convert ----------------
#define CVT_ADJ  4194304
#define CVT_SEQ  524288
#define CVT_W    65536
#define CVT_TOT  (2 * CVT_ADJ + 2 * CVT_SEQ + 2 * CVT_W)

__global__ void k_cvt_all(const float4* __restrict__ adj, const float4* __restrict__ dif,
                          const float4* __restrict__ s1,  const float4* __restrict__ s2,
                          const float4* __restrict__ w1,  const float4* __restrict__ w2)
{
    long off = (long)blockIdx.x * 256 + threadIdx.x;
    const float4* src; float4* dst;
    if (off < CVT_ADJ)                   { src = adj; dst = (float4*)g_adjc; }
    else if ((off -= CVT_ADJ) < CVT_ADJ) { src = dif; dst = (float4*)g_diffc; }
    else if ((off -= CVT_ADJ) < CVT_SEQ) { src = s1;  dst = (float4*)g_seqc[0]; }
    else if ((off -= CVT_SEQ) < CVT_SEQ) { src = s2;  dst = (float4*)g_seqc[1]; }
    else if ((off -= CVT_SEQ) < CVT_W)   { src = w1;  dst = (float4*)g_Wc[0]; }
    else if ((off -= CVT_W) < CVT_W)     { src = w2;  dst = (float4*)g_Wc[1]; }
    else return;
    float4 v = src[off];
    v.x = __uint_as_float(f2tf32(v.x));
    v.y = __uint_as_float(f2tf32(v.y));
    v.z = __uint_as_float(f2tf32(v.z));
    v.w = __uint_as_float(f2tf32(v.w));
    dst[off] = v;
}

// ---------------- ftsT[z] = W[z] x seq[z]^T : M=512, N=4096, K=512 ----------------
__global__ __launch_bounds__(256, 2) void k_gemm_ftsT() {
    const int z = blockIdx.z;
    const float* A = g_Wc[z & 1];
    const float* B = g_seqc[z >> 1];
    float* __restrict__ C = g_fts[z];
    const int m0 = blockIdx.y * 128, n0 = blockIdx.x * 128;

    float acc[4][4][4];
    ZERO_ACC4(acc);
    nt_core(A, N_INF, B, N_INF, m0, n0, N_INF, acc);

    const int lane = threadIdx.x & 31, warp = threadIdx.x >> 5;
    const int g = lane >> 2, t4 = lane & 3;
    const int wr = (warp & 1) * 64, wc = (warp >> 1) * 32;
#pragma unroll
    for (int mt = 0; mt < 4; mt++)
#pragma unroll
        for (int nt = 0; nt < 4; nt++) {
            int row = m0 + wr + mt * 16 + g;
            int col = n0 + wc + nt * 8 + 2 * t4;
            float2 v01, v23;
            v01.x = __uint_as_float(f2tf32(acc[mt][nt][0]));
            v01.y = __uint_as_float(f2tf32(acc[mt][nt][1]));
            v23.x = __uint_as_float(f2tf32(acc[mt][nt][2]));
            v23.y = __uint_as_float(f2tf32(acc[mt][nt][3]));
            *(float2*)(C + (size_t)row * N_NODES + col) = v01;
            *(float2*)(C + (size_t)(row + 8) * N_NODES + col) = v23;
        }
}

// ---------------- h[z] = prelu(adj x ftsT^T + b): M=4096, N=512, K=4096 ------------
__global__ __launch_bounds__(256, 2) void k_gemm_prop(
    const float* __restrict__ b1,  const float* __restrict__ b2,
    const float* __restrict__ a1,  const float* __restrict__ a2)
{
    const int z = blockIdx.z;
    const float* A = (z & 1) ? g_diffc : g_adjc;
    const float* B = g_fts[z];
    const float* bias = (z & 1) ? b2 : b1;
    const float slope = (z & 1) ? a2[0] : a1[0];
    float* __restrict__ C = g_h[z];
    const int m0 = blockIdx.y * 128, n0 = blockIdx.x * 128;

    float acc[4][4][4];
    ZERO_ACC4(acc);
    nt_core(A, N_NODES, B, N_NODES, m0, n0, N_NODES, acc);

    const int lane = threadIdx.x & 31, warp = threadIdx.x >> 5;
    const int g = lane >> 2, t4 = lane & 3;
    const int wr = (warp & 1) * 64, wc = (warp >> 1) * 32;
#pragma unroll
    for (int mt = 0; mt < 4; mt++)
#pragma unroll
        for (int nt = 0; nt < 4; nt++) {
            int row = m0 + wr + mt * 16 + g;
            int col = n0 + wc + nt * 8 + 2 * t4;
            float b0 = bias[col], b1v = bias[col + 1];
            float2 v01, v23;
            v01.x = acc[mt][nt][0] + b0;  v01.y = acc[mt][nt][1] + b1v;
            v23.x = acc[mt][nt][2] + b0;  v23.y = acc[mt][nt][3] + b1v;
            v01.x = (v01.x >= 0.0f) ? v01.x : slope * v01.x;
            v01.y = (v01.y >= 0.0f) ? v01.y : slope * v01.y;
            v23.x = (v23.x >= 0.0f) ? v23.x : slope * v23.x;
            v23.y = (v23.y >= 0.0f) ? v23.y : slope * v23.y;
            *(float2*)(C + (size_t)row * N_HID + col) = v01;
            *(float2*)(C + (size_t)(row + 8) * N_HID + col) = v23;
        }
}

// ---------------- node_sq = (Zn Zn^T)^2: M=N=4096, K=512 ----------------
__global__ __launch_bounds__(256, 2) void k_gemm_node() {
    const int m0 = blockIdx.y * 128, n0 = blockIdx.x * 128;

    float acc[4][4][4];
    ZERO_ACC4(acc);
    nt_core(g_Z, N_HID, g_Z, N_HID, m0, n0, N_HID, acc);

    const int lane = threadIdx.x & 31, warp = threadIdx.x >> 5;
    const int g = lane >> 2, t4 = lane & 3;
    const int wr = (warp & 1) * 64, wc = (warp >> 1) * 32;
#pragma unroll
    for (int mt = 0; mt < 4; mt++) {
        int row = m0 + wr + mt * 16 + g;
        float ri0 = g_rninv[row], ri1 = g_rninv[row + 8];
#pragma unroll
        for (int nt = 0; nt < 4; nt++) {
            int col = n0 + wc + nt * 8 + 2 * t4;
            float c0 = g_rninv[col], c1 = g_rninv[col + 1];
            float x0 = acc[mt][nt][0] * ri0 * c0;
            float x1 = acc[mt][nt][1] * ri0 * c1;
            float x2 = acc[mt][nt][2] * ri1 * c0;
            float x3 = acc[mt][nt][3] * ri1 * c1;
            float2 v01, v23;
            v01.x = x0 * x0; v01.y = x1 * x1;
            v23.x = x2 * x2; v23.y = x3 * x3;
            *(float2*)(g_node_sq + (size_t)row * N_NODES + col) = v01;
            *(float2*)(g_node_sq + (size_t)(row + 8) * N_NODES + col) = v23;
        }
    }
}

// ---------------- Z = h1 + h2 (tf32-rounded), row inv-norms ----------------
__global__ void k_compute_Z() {
    const int r = blockIdx.x;
    const int c = threadIdx.x;
    float z = g_h[0][(size_t)r * N_HID + c] + g_h[1][(size_t)r * N_HID + c];
    float zr = __uint_as_float(f2tf32(z));
    g_Z[(size_t)r * N_HID + c] = zr;
    __shared__ float red[512];
    red[c] = zr * zr;
    __syncthreads();
    for (int s = 256; s > 0; s >>= 1) {
        if (c < s) red[c] += red[c + s];
        __syncthreads();
    }
    if (c == 0) g_rninv[r] = 1.0f / fmaxf(sqrtf(red[0]), 1e-12f);
}

// ---------------- column reductions ----------------
__global__ void k_col_reduce() {
    const int mode = blockIdx.y;
    const int tx = threadIdx.x & 31;
    const int ty = threadIdx.x >> 5;
    const int col = blockIdx.x * 32 + tx;
    const float* __restrict__ src = (mode == 0) ? g_h[0] : (mode == 1) ? g_h[1] : g_Z;
    float s = 0.0f;
    for (int r = ty; r < N_NODES; r += 8) {
        float v = src[(size_t)r * N_HID + col];
        s += (mode == 2) ? v * v : v;
    }
    __shared__ float sm[8][32];
    sm[ty][tx] = s;
    __syncthreads();
    if (ty == 0) {
        float tot = 0.0f;
#pragma unroll
        for (int k = 0; k < 8; k++) tot += sm[k][tx];
        if (mode == 2) g_cninv[col] = 1.0f / fmaxf(sqrtf(tot), 1e-12f);
        else g_csum[mode][col] = tot;
    }
}

// ---------------- u = Wd @ sigmoid(colmean) ----------------
__global__ void k_compute_u(const float* __restrict__ Wd) {
    __shared__ float c1s[512], c2s[512];
    const int h = threadIdx.x;
    c1s[h] = 1.0f / (1.0f + expf(-g_csum[0][h] * (1.0f / 4096.0f)));
    c2s[h] = 1.0f / (1.0f + expf(-g_csum[1][h] * (1.0f / 4096.0f)));
    __syncthreads();
    float u1 = 0.0f, u2 = 0.0f;
    const float4* Wrow = reinterpret_cast<const float4*>(Wd + (size_t)h * N_HID);
#pragma unroll 4
    for (int k4 = 0; k4 < 128; k4++) {
        float4 w = Wrow[k4];
        int k = k4 * 4;
        u1 += w.x * c1s[k] + w.y * c1s[k + 1] + w.z * c1s[k + 2] + w.w * c1s[k + 3];
        u2 += w.x * c2s[k] + w.y * c2s[k + 1] + w.z * c2s[k + 2] + w.w * c2s[k + 3];
    }
    g_u[0][h] = u1;
    g_u[1][h] = u2;
}

// ---------------- ret ----------------
__global__ void k_ret(const float* __restrict__ bd, float* __restrict__ out) {
    const int q = blockIdx.y;
    const int n = blockIdx.x * 8 + (threadIdx.x >> 5);
    const int lane = threadIdx.x & 31;
    const float* __restrict__ h = (q == 0) ? g_h[1] : (q == 1) ? g_h[0]
                                : (q == 2) ? g_h[3] : g_h[2];
    const float* __restrict__ u = (q == 0 || q == 2) ? g_u[0] : g_u[1];
    float s = 0.0f;
    for (int k = lane; k < N_HID; k += 32)
        s += h[(size_t)n * N_HID + k] * u[k];
#pragma unroll
    for (int o = 16; o > 0; o >>= 1) s += __shfl_down_sync(0xFFFFFFFFu, s, o);
    if (lane == 0) out[q * N_NODES + n] = s + bd[0];
}

// ---------------- mma.sync TN core for G = Z^T Z (small) ----------------
#define CVT_ST4(dst, row, seg, v)                        \
    dst[row][(seg) + 0] = f2tf32(v.x);                   \
    dst[row][(seg) + 1] = f2tf32(v.y);                   \
    dst[row][(seg) + 2] = f2tf32(v.z);                   \
    dst[row][(seg) + 3] = f2tf32(v.w);

__global__ __launch_bounds__(256) void k_gemm_G() {
    __shared__ unsigned As[2][16][136];
    __shared__ unsigned Bs[2][16][136];
    const int t = threadIdx.x;
    const int lane = t & 31, warp = t >> 5;
    const int g = lane >> 2, t4 = lane & 3;
    const int wr = (warp & 1) * 64, wc = (warp >> 1) * 32;
    const int kr = t >> 5, nseg = (t & 31) * 4;
    const int m0 = blockIdx.y * 128, n0 = blockIdx.x * 128;
    const float* Zk = g_Z + (size_t)blockIdx.z * 512 * N_HID;

    const float* Ab = Zk + (size_t)kr * N_HID + m0 + nseg;
    const float* Bb = Zk + (size_t)kr * N_HID + n0 + nseg;

    float acc[4][4][4];
#pragma unroll
    for (int mt = 0; mt < 4; mt++)
#pragma unroll
        for (int nt = 0; nt < 4; nt++)
#pragma unroll
            for (int e = 0; e < 4; e++) acc[mt][nt][e] = 0.0f;

    {
        float4 a0 = *(const float4*)(Ab);
        float4 a1 = *(const float4*)(Ab + (size_t)8 * N_HID);
        float4 b0 = *(const float4*)(Bb);
        float4 b1 = *(const float4*)(Bb + (size_t)8 * N_HID);
        CVT_ST4(As[0], kr, nseg, a0); CVT_ST4(As[0], kr + 8, nseg, a1);
        CVT_ST4(Bs[0], kr, nseg, b0); CVT_ST4(Bs[0], kr + 8, nseg, b1);
    }
    __syncthreads();
    for (int kt = 0; kt < 32; kt++) {
        const int cur = kt & 1;
        float4 a0, a1, b0, b1;
        const bool pf = (kt + 1 < 32);
        if (pf) {
            const float* Ap = Ab + (size_t)(kt + 1) * 16 * N_HID;
            const float* Bp = Bb + (size_t)(kt + 1) * 16 * N_HID;
            a0 = *(const float4*)Ap; a1 = *(const float4*)(Ap + (size_t)8 * N_HID);
            b0 = *(const float4*)Bp; b1 = *(const float4*)(Bp + (size_t)8 * N_HID);
        }
#pragma unroll
        for (int ks = 0; ks < 2; ks++) {
            const int k = ks * 8;
            unsigned af[4][4], bf[4][2];
#pragma unroll
            for (int mt = 0; mt < 4; mt++) {
                const int r = wr + mt * 16;
                af[mt][0] = As[cur][k + t4][r + g];
                af[mt][1] = As[cur][k + t4][r + g + 8];
                af[mt][2] = As[cur][k + t4 + 4][r + g];
                af[mt][3] = As[cur][k + t4 + 4][r + g + 8];
            }
#pragma unroll
            for (int nt = 0; nt < 4; nt++) {
                const int c = wc + nt * 8 + g;
                bf[nt][0] = Bs[cur][k + t4][c];
                bf[nt][1] = Bs[cur][k + t4 + 4][c];
            }
#pragma unroll
            for (int mt = 0; mt < 4; mt++)
#pragma unroll
                for (int nt = 0; nt < 4; nt++)
                    mma8(acc[mt][nt], af[mt], bf[nt]);
        }
        if (pf) {
            const int nxt = cur ^ 1;
            CVT_ST4(As[nxt], kr, nseg, a0); CVT_ST4(As[nxt], kr + 8, nseg, a1);
            CVT_ST4(Bs[nxt], kr, nseg, b0); CVT_ST4(Bs[nxt], kr + 8, nseg, b1);
        }
        __syncthreads();
    }
#pragma unroll
    for (int mt = 0; mt < 4; mt++)
#pragma unroll
        for (int nt = 0; nt < 4; nt++)
#pragma unroll
            for (int e = 0; e < 4; e++) {
                int row = m0 + wr + mt * 16 + g + (e >> 1) * 8;
                int col = n0 + wc + nt * 8 + 2 * t4 + (e & 1);
                atomicAdd(&g_G[(size_t)row * N_HID + col], acc[mt][nt][e]);
            }
}

// ---------------- feat loss ----------------
__global__ void k_feat_loss(const int* __restrict__ feat_index) {
    const int h = blockIdx.x;
    const int k = threadIdx.x;
    __shared__ float sv[512];
    float feat = g_G[(size_t)h * N_HID + k] * g_cninv[h] * g_cninv[k];
    sv[k] = feat * feat;
    __syncthreads();
    const float diag = sv[h];
    __syncthreads();
    for (int kk = 2; kk <= 512; kk <<= 1) {
        for (int j = kk >> 1; j > 0; j >>= 1) {
            int i = k;
            int ixj = i ^ j;
            if (ixj > i) {
                float a = sv[i], b = sv[ixj];
                bool up = ((i & kk) == 0);
                if ((a > b) == up) { sv[i] = b; sv[ixj] = a; }
            }
            __syncthreads();
        }
    }
    if (k == 0) {
        float neg = 0.0f;
#pragma unroll
        for (int s = 0; s < N_S; s++) neg += expf(2.0f * sv[feat_index[s]]);
        float pos = expf(2.0f * diag);
        atomicAdd(&g_feat_loss, (logf(neg) - logf(pos)) * (1.0f / 512.0f));
    }
}

// ---------------- node loss: register/shuffle bitonic ----------------
__global__ __launch_bounds__(512) void k_node_sel(const float* __restrict__ adj_label,
                                                  const int* __restrict__ node_index) {
    const int i = blockIdx.x;
    const int t = threadIdx.x;
    __shared__ float sm[4096];
    __shared__ float red[512];
    const float* __restrict__ trow = g_node_sq + (size_t)i * N_NODES;
    const float* __restrict__ lrow = adj_label + (size_t)i * N_NODES;

    float v[8];
    float pos = 0.0f;
    {
        const float4* t4p = reinterpret_cast<const float4*>(trow) + t * 2;
        const float4* l4p = reinterpret_cast<const float4*>(lrow) + t * 2;
        float4 a = t4p[0], b = t4p[1];
        float4 la = l4p[0], lb = l4p[1];
        v[0] = a.x; v[1] = a.y; v[2] = a.z; v[3] = a.w;
        v[4] = b.x; v[5] = b.y; v[6] = b.z; v[7] = b.w;
        pos += __expf(2.0f * a.x) * la.x + __expf(2.0f * a.y) * la.y
             + __expf(2.0f * a.z) * la.z + __expf(2.0f * a.w) * la.w
             + __expf(2.0f * b.x) * lb.x + __expf(2.0f * b.y) * lb.y
             + __expf(2.0f * b.z) * lb.z + __expf(2.0f * b.w) * lb.w;
    }
    red[t] = pos;
    __syncthreads();
    for (int s = 256; s > 0; s >>= 1) {
        if (t < s) red[t] += red[t + s];
        __syncthreads();
    }
    const float posSum = red[0];

    for (int kk = 2; kk <= 4096; kk <<= 1) {
        for (int j = kk >> 1; j > 0; j >>= 1) {
            if (j >= 256) {
                const int d = j >> 3;
                const bool lower = (t & d) == 0;
                const bool up = ((t & (kk >> 3)) == 0);
                const bool keepmin = (up == lower);
                __syncthreads();
#pragma unroll
                for (int e = 0; e < 8; e++) sm[t * 8 + e] = v[e];
                __syncthreads();
#pragma unroll
                for (int e = 0; e < 8; e++) {
                    float o = sm[(t ^ d) * 8 + e];
                    v[e] = keepmin ? fminf(v[e], o) : fmaxf(v[e], o);
                }
            } else if (j >= 8) {
                const int d = j >> 3;
                const bool lower = (t & d) == 0;
                const bool up = ((t & (kk >> 3)) == 0);
                const bool keepmin = (up == lower);
#pragma unroll
                for (int e = 0; e < 8; e++) {
                    float o = __shfl_xor_sync(0xFFFFFFFFu, v[e], d);
                    v[e] = keepmin ? fminf(v[e], o) : fmaxf(v[e], o);
                }
            } else {
#pragma unroll
                for (int e = 0; e < 8; e++) {
                    if ((e & j) == 0) {
                        int p = e | j;
                        bool up = ((((t << 3) | e) & kk) == 0);
                        float a = v[e], b = v[p];
                        float lo = fminf(a, b), hi = fmaxf(a, b);
                        v[e] = up ? lo : hi;
                        v[p] = up ? hi : lo;
                    }
                }
            }
        }
    }
    __syncthreads();
#pragma unroll
    for (int e = 0; e < 8; e++) sm[t * 8 + e] = v[e];
    __syncthreads();
    if (t == 0) {
        float neg = 0.0f;
#pragma unroll
        for (int s = 0; s < N_S; s++) neg += __expf(2.0f * sm[node_index[s]]);
        atomicAdd(&g_node_loss, (logf(neg) - logf(posSum)) * (1.0f / 4096.0f));
    }
}

// ---------------- finalize ----------------
__global__ void k_finalize(float* __restrict__ out) {
    out[4 * N_NODES + 0] = g_feat_loss;
    out[4 * N_NODES + 1] = g_node_loss;
}

// ---------------- launch ----------------
extern "C" void kernel_launch(void* const* d_in, const int* in_sizes, int n_in,
                              void* d_out, int out_size) {
    const float* seq1      = (const float*)d_in[0];
    const float* seq2      = (const float*)d_in[1];
    const float* adj       = (const float*)d_in[2];
    const float* diff      = (const float*)d_in[3];
    const float* adj_label = (const float*)d_in[4];
    const int*   feat_idx  = (const int*)d_in[5];
    const int*   node_idx  = (const int*)d_in[6];
    const float* b1        = (const float*)d_in[8];
    const float* a1        = (const float*)d_in[9];
    const float* b2        = (const float*)d_in[11];
    const float* a2        = (const float*)d_in[12];
    const float* Wd        = (const float*)d_in[13];
    const float* bd        = (const float*)d_in[14];
    float* out = (float*)d_out;

    cudaFuncSetAttribute(k_gemm_ftsT, cudaFuncAttributeMaxDynamicSharedMemorySize, SMEM_TOTAL_G);
    cudaFuncSetAttribute(k_gemm_prop, cudaFuncAttributeMaxDynamicSharedMemorySize, SMEM_TOTAL_G);
    cudaFuncSetAttribute(k_gemm_node, cudaFuncAttributeMaxDynamicSharedMemorySize, SMEM_TOTAL_G);

    // launch #4 = k_gemm_prop (observed ncu capture slot)
    k_cvt_all<<<(CVT_TOT + 255) / 256, 256>>>(
        (const float4*)adj, (const float4*)diff,
        (const float4*)seq1, (const float4*)seq2,
        (const float4*)d_in[7], (const float4*)d_in[10]);
    k_init<<<(N_HID * N_HID + 255) / 256, 256>>>();
    k_gemm_ftsT<<<dim3(32, 4, 4), 256, SMEM_TOTAL_G>>>();
    k_gemm_prop<<<dim3(4, 32, 4), 256, SMEM_TOTAL_G>>>(b1, b2, a1, a2);
    k_compute_Z<<<N_NODES, 512>>>();
    k_col_reduce<<<dim3(16, 3), 256>>>();
    k_compute_u<<<1, 512>>>(Wd);
    k_ret<<<dim3(512, 4), 256>>>(bd, out);
    k_gemm_G<<<dim3(4, 4, 8), 256>>>();
    k_feat_loss<<<512, 512>>>(feat_idx);
    k_gemm_node<<<dim3(32, 32), 256, SMEM_TOTAL_G>>>();
    k_node_sel<<<N_NODES, 512>>>(adj_label, node_idx);
    k_finalize<<<1, 1>>>(out);
}